// round 1
// baseline (speedup 1.0000x reference)
#include <cuda_runtime.h>
#include <math.h>

// Problem constants (match reference setup_inputs)
#define Nn 100000
#define Ee 600000
#define IN_DIM 64
#define Hd 128
#define Ld 3
#define Gg 256
#define Cc 10

// ---------------- device scratch (static, no runtime allocation) ----------------
__device__ float  g_h[(size_t)Nn * Hd];           // node features between layers
__device__ float  g_qkvs[(size_t)Nn * 4 * Hd];    // [N, 512]: q | k | v | skip
__device__ float  g_agg[(size_t)Nn * Hd];         // attention aggregation
__device__ float  g_ea[Ee];                       // per-edge score / exp
__device__ float  g_m[Nn];                        // per-node max
__device__ float  g_sden[Nn];                     // per-node softmax denom
__device__ double g_sum[Hd];                      // BN channel sums
__device__ double g_sumsq[Hd];
__device__ float  g_scale[Hd];                    // folded BN scale
__device__ float  g_shift[Hd];                    // folded BN shift
__device__ float  g_pool[Gg * Hd];
__device__ float  g_cnt[Gg];

// ---------------- helpers ----------------
__device__ __forceinline__ void atomicMaxFloat(float* addr, float val) {
    int* ia = (int*)addr;
    int old = *ia;
    while (__int_as_float(old) < val) {
        int assumed = old;
        old = atomicCAS(ia, assumed, __float_as_int(val));
        if (old == assumed) break;
    }
}

// ---------------- per-layer init ----------------
__global__ void layer_init(int n) {
    long stride = (long)gridDim.x * blockDim.x;
    long idx = (long)blockIdx.x * blockDim.x + threadIdx.x;
    long total = (long)n * Hd;
    for (long i = idx; i < total; i += stride) g_agg[i] = 0.f;
    for (long i = idx; i < n; i += stride) { g_m[i] = -INFINITY; g_sden[i] = 0.f; }
    if (idx < Hd) { g_sum[idx] = 0.0; g_sumsq[idx] = 0.0; }
}

// ---------------- fused QKVS GEMM: C[N,512] = A[N,K] @ [Wq|Wk|Wv|Ws] + bias ----------------
#define BM 128
#define BN 128
#define BK 8

__global__ void __launch_bounds__(256) gemm_qkvs(
    const float* __restrict__ Ain, int n, int K,
    const float* __restrict__ Wq, const float* __restrict__ Wk,
    const float* __restrict__ Wv, const float* __restrict__ Ws,
    const float* __restrict__ bq, const float* __restrict__ bk,
    const float* __restrict__ bv, const float* __restrict__ bs)
{
    const float* A = Ain ? Ain : g_h;
    const float* W;
    const float* bias;
    switch (blockIdx.y) {
        case 0:  W = Wq; bias = bq; break;
        case 1:  W = Wk; bias = bk; break;
        case 2:  W = Wv; bias = bv; break;
        default: W = Ws; bias = bs; break;
    }

    __shared__ float As[BK][BM];
    __shared__ float Bs[BK][BN];

    const int tid  = threadIdx.x;
    const int row0 = blockIdx.x * BM;
    const int tx = tid % 16;
    const int ty = tid / 16;

    float acc[8][8];
    #pragma unroll
    for (int i = 0; i < 8; i++)
        #pragma unroll
        for (int j = 0; j < 8; j++) acc[i][j] = 0.f;

    const int a_m = tid >> 1;           // 0..127
    const int a_k = (tid & 1) * 4;      // 0 or 4
    const int b_k = tid >> 5;           // 0..7
    const int b_n = (tid & 31) * 4;     // 0..124

    for (int kt = 0; kt < K; kt += BK) {
        float4 av = make_float4(0.f, 0.f, 0.f, 0.f);
        int grow = row0 + a_m;
        if (grow < n) av = *(const float4*)(A + (size_t)grow * K + kt + a_k);
        As[a_k + 0][a_m] = av.x;
        As[a_k + 1][a_m] = av.y;
        As[a_k + 2][a_m] = av.z;
        As[a_k + 3][a_m] = av.w;

        float4 bv4 = *(const float4*)(W + (size_t)(kt + b_k) * Hd + b_n);
        *(float4*)&Bs[b_k][b_n] = bv4;

        __syncthreads();

        #pragma unroll
        for (int k = 0; k < BK; k++) {
            float ra[8], rb[8];
            #pragma unroll
            for (int i = 0; i < 8; i++) ra[i] = As[k][ty * 8 + i];
            #pragma unroll
            for (int j = 0; j < 8; j++) rb[j] = Bs[k][tx * 8 + j];
            #pragma unroll
            for (int i = 0; i < 8; i++)
                #pragma unroll
                for (int j = 0; j < 8; j++)
                    acc[i][j] += ra[i] * rb[j];
        }
        __syncthreads();
    }

    #pragma unroll
    for (int i = 0; i < 8; i++) {
        int r = row0 + ty * 8 + i;
        if (r >= n) continue;
        #pragma unroll
        for (int j = 0; j < 8; j += 4) {
            int col = tx * 8 + j;
            float4 o;
            o.x = acc[i][j + 0] + bias[col + 0];
            o.y = acc[i][j + 1] + bias[col + 1];
            o.z = acc[i][j + 2] + bias[col + 2];
            o.w = acc[i][j + 3] + bias[col + 3];
            *(float4*)(g_qkvs + (size_t)r * 512 + blockIdx.y * Hd + col) = o;
        }
    }
}

// ---------------- edge attention passes ----------------
__global__ void attn_score(const int* __restrict__ src, const int* __restrict__ dst, int E) {
    int e = (blockIdx.x * blockDim.x + threadIdx.x) >> 5;
    int lane = threadIdx.x & 31;
    if (e >= E) return;
    int sN = src[e], dN = dst[e];
    float4 q = *(const float4*)(g_qkvs + (size_t)dN * 512 + lane * 4);
    float4 k = *(const float4*)(g_qkvs + (size_t)sN * 512 + Hd + lane * 4);
    float p = q.x * k.x + q.y * k.y + q.z * k.z + q.w * k.w;
    #pragma unroll
    for (int o = 16; o; o >>= 1) p += __shfl_xor_sync(0xffffffffu, p, o);
    if (lane == 0) {
        p *= 0.08838834764831845f;   // 1/sqrt(128)
        g_ea[e] = p;
        atomicMaxFloat(&g_m[dN], p);
    }
}

__global__ void attn_exp(const int* __restrict__ dst, int E) {
    int e = blockIdx.x * blockDim.x + threadIdx.x;
    if (e >= E) return;
    int dN = dst[e];
    float w = expf(g_ea[e] - g_m[dN]);
    g_ea[e] = w;
    atomicAdd(&g_sden[dN], w);
}

__global__ void attn_agg(const int* __restrict__ src, const int* __restrict__ dst, int E) {
    int e = (blockIdx.x * blockDim.x + threadIdx.x) >> 5;
    int lane = threadIdx.x & 31;
    if (e >= E) return;
    int sN = src[e], dN = dst[e];
    float w = g_ea[e] / g_sden[dN];
    float4 v = *(const float4*)(g_qkvs + (size_t)sN * 512 + 2 * Hd + lane * 4);
    float* dp = g_agg + (size_t)dN * Hd + lane * 4;
    atomicAdd(dp + 0, v.x * w);
    atomicAdd(dp + 1, v.y * w);
    atomicAdd(dp + 2, v.z * w);
    atomicAdd(dp + 3, v.w * w);
}

// ---------------- BN (training-mode) ----------------
__global__ void __launch_bounds__(256) bn_pre(int n) {
    int c = threadIdx.x & 127;
    int half = threadIdx.x >> 7;
    double s = 0.0, ss = 0.0;
    for (int i = blockIdx.x * 2 + half; i < n; i += gridDim.x * 2) {
        float v = g_agg[(size_t)i * Hd + c] + g_qkvs[(size_t)i * 512 + 3 * Hd + c];
        g_h[(size_t)i * Hd + c] = v;
        s += v;
        ss += (double)v * (double)v;
    }
    __shared__ double sh[256], sh2[256];
    sh[threadIdx.x] = s; sh2[threadIdx.x] = ss;
    __syncthreads();
    if (half == 0) {
        s  += sh[128 + c];
        ss += sh2[128 + c];
        atomicAdd(&g_sum[c], s);
        atomicAdd(&g_sumsq[c], ss);
    }
}

__global__ void bn_stats(int n, const float* __restrict__ gamma, const float* __restrict__ beta) {
    int c = threadIdx.x;
    if (c >= Hd) return;
    double mean = g_sum[c] / n;
    double var  = g_sumsq[c] / n - mean * mean;
    if (var < 0.0) var = 0.0;
    float inv = (float)rsqrt(var + 1e-5);
    float sc = inv * gamma[c];
    g_scale[c] = sc;
    g_shift[c] = beta[c] - (float)mean * sc;
}

__global__ void bn_apply(int n) {
    long stride = (long)gridDim.x * blockDim.x;
    long total = (long)n * Hd;
    for (long i = (long)blockIdx.x * blockDim.x + threadIdx.x; i < total; i += stride) {
        int c = (int)(i & 127);
        float v = g_h[i] * g_scale[c] + g_shift[c];
        g_h[i] = fmaxf(v, 0.f);
    }
}

// ---------------- pooling + classifier ----------------
__global__ void pool_init() {
    int idx = blockIdx.x * blockDim.x + threadIdx.x;
    if (idx < Gg * Hd) g_pool[idx] = 0.f;
    if (idx < Gg) g_cnt[idx] = 0.f;
}

__global__ void pool_accum(const int* __restrict__ batch, int n) {
    long stride = (long)gridDim.x * blockDim.x;
    long total = (long)n * Hd;
    for (long idx = (long)blockIdx.x * blockDim.x + threadIdx.x; idx < total; idx += stride) {
        int i = (int)(idx >> 7);
        int c = (int)(idx & 127);
        int b = batch[i];
        atomicAdd(&g_pool[b * Hd + c], g_h[idx]);
        if (c == 0) atomicAdd(&g_cnt[b], 1.f);
    }
}

__global__ void classify(const float* __restrict__ W, const float* __restrict__ b,
                         float* __restrict__ out) {
    int g = blockIdx.x;
    int c = threadIdx.x;
    if (c >= Cc) return;
    float inv = 1.f / fmaxf(g_cnt[g], 1.f);
    float acc = 0.f;
    #pragma unroll 8
    for (int h = 0; h < Hd; h++) acc += g_pool[g * Hd + h] * W[h * Cc + c];
    out[g * Cc + c] = acc * inv + b[c];
}

// ---------------- host orchestration ----------------
static void run_layer(const float* hin, int K, int n, int E,
                      const int* src, const int* dst,
                      const float* Wq, const float* bq,
                      const float* Wk, const float* bk,
                      const float* Wv, const float* bv,
                      const float* Ws, const float* bs,
                      const float* bng, const float* bnb)
{
    layer_init<<<512, 256>>>(n);
    dim3 gg((n + BM - 1) / BM, 4);
    gemm_qkvs<<<gg, 256>>>(hin, n, K, Wq, Wk, Wv, Ws, bq, bk, bv, bs);
    long ethreads = (long)E * 32;
    attn_score<<<(unsigned)((ethreads + 255) / 256), 256>>>(src, dst, E);
    attn_exp<<<(E + 255) / 256, 256>>>(dst, E);
    attn_agg<<<(unsigned)((ethreads + 255) / 256), 256>>>(src, dst, E);
    bn_pre<<<256, 256>>>(n);
    bn_stats<<<1, 128>>>(n, bng, bnb);
    bn_apply<<<512, 256>>>(n);
}

extern "C" void kernel_launch(void* const* d_in, const int* in_sizes, int n_in,
                              void* d_out, int out_size)
{
    const float* x     = (const float*)d_in[0];
    const int*   ei    = (const int*)d_in[1];
    const int*   batch = (const int*)d_in[2];
    const float* Wq1 = (const float*)d_in[3];
    const float* bq1 = (const float*)d_in[4];
    const float* Wk1 = (const float*)d_in[5];
    const float* bk1 = (const float*)d_in[6];
    const float* Wv1 = (const float*)d_in[7];
    const float* bv1 = (const float*)d_in[8];
    const float* Ws1 = (const float*)d_in[9];
    const float* bs1 = (const float*)d_in[10];
    const float* bn1g = (const float*)d_in[11];
    const float* bn1b = (const float*)d_in[12];
    const float* Wq = (const float*)d_in[13];
    const float* bq = (const float*)d_in[14];
    const float* Wk = (const float*)d_in[15];
    const float* bk = (const float*)d_in[16];
    const float* Wv = (const float*)d_in[17];
    const float* bv = (const float*)d_in[18];
    const float* Ws = (const float*)d_in[19];
    const float* bs = (const float*)d_in[20];
    const float* bng = (const float*)d_in[21];
    const float* bnb = (const float*)d_in[22];
    const float* linW = (const float*)d_in[23];
    const float* linb = (const float*)d_in[24];

    int n = in_sizes[0] / IN_DIM;
    int E = in_sizes[1] / 2;
    const int* src = ei;
    const int* dst = ei + E;

    // layer 1: IN_DIM -> H
    run_layer(x, IN_DIM, n, E, src, dst,
              Wq1, bq1, Wk1, bk1, Wv1, bv1, Ws1, bs1, bn1g, bn1b);

    // hidden layers: H -> H
    for (int i = 0; i < Ld; i++) {
        run_layer(nullptr, Hd, n, E, src, dst,
                  Wq + (size_t)i * Hd * Hd, bq + i * Hd,
                  Wk + (size_t)i * Hd * Hd, bk + i * Hd,
                  Wv + (size_t)i * Hd * Hd, bv + i * Hd,
                  Ws + (size_t)i * Hd * Hd, bs + i * Hd,
                  bng + i * Hd, bnb + i * Hd);
    }

    // global mean pool + classifier
    pool_init<<<(Gg * Hd + 255) / 256, 256>>>();
    pool_accum<<<1024, 256>>>(batch, n);
    classify<<<Gg, 32>>>(linW, linb, (float*)d_out);
}

// round 3
// speedup vs baseline: 1.2061x; 1.2061x over previous
#include <cuda_runtime.h>
#include <cuda_bf16.h>
#include <math.h>
#include <stdint.h>

// Problem constants
#define Nn 100000
#define Ee 600000
#define IN_DIM 64
#define Hd 128
#define Ld 3
#define Gg 256
#define Cc 10
#define NTILES ((Nn + 127) / 128)

// ---------------- device scratch ----------------
__device__ float  g_h[(size_t)Nn * Hd];
__device__ float  g_qkvs[(size_t)Nn * 4 * Hd];    // [N,512]: q|k|v|s
__device__ float  g_agg[(size_t)Nn * Hd];
__device__ float  g_ea[Ee];
__device__ float  g_m[Nn];
__device__ float  g_sden[Nn];
__device__ double g_sum[Hd];
__device__ double g_sumsq[Hd];
__device__ float  g_scale[Hd];
__device__ float  g_shift[Hd];
__device__ float  g_pool[Gg * Hd];
__device__ float  g_cnt[Gg];
// bf16 hi/lo split staging for MMA GEMM (plain K-major layouts)
__device__ __nv_bfloat16 g_Ahi[(size_t)NTILES * 128 * 128];
__device__ __nv_bfloat16 g_Alo[(size_t)NTILES * 128 * 128];
__device__ __nv_bfloat16 g_Bhi[512 * 128];
__device__ __nv_bfloat16 g_Blo[512 * 128];
__device__ float  g_bias[512];

// ---------------- mma.sync helper ----------------
__device__ __forceinline__ void mma16816(float* d,
    uint32_t a0, uint32_t a1, uint32_t a2, uint32_t a3,
    uint32_t b0, uint32_t b1)
{
    asm volatile(
        "mma.sync.aligned.m16n8k16.row.col.f32.bf16.bf16.f32 "
        "{%0,%1,%2,%3}, {%4,%5,%6,%7}, {%8,%9}, {%0,%1,%2,%3};"
        : "+f"(d[0]), "+f"(d[1]), "+f"(d[2]), "+f"(d[3])
        : "r"(a0), "r"(a1), "r"(a2), "r"(a3), "r"(b0), "r"(b1));
}

// ---------------- prep kernels: fp32 -> bf16 hi/lo split ----------------
template<int K>
__global__ void prep_A(const float* __restrict__ src, int n, int ntiles) {
    long total = (long)ntiles * 128 * K;
    long idx = (long)blockIdx.x * blockDim.x + threadIdx.x;
    if (idx >= total) return;
    long i = idx / K;
    int  k = (int)(idx % K);
    float v = (i < n) ? src[i * K + k] : 0.f;
    __nv_bfloat16 hi = __float2bfloat16(v);
    __nv_bfloat16 lo = __float2bfloat16(v - __bfloat162float(hi));
    g_Ahi[idx] = hi;
    g_Alo[idx] = lo;
}

__global__ void zero_padA(int n, int ntiles) {
    long start = (long)n * Hd;
    long total = (long)ntiles * 128 * Hd;
    long idx = start + (long)blockIdx.x * blockDim.x + threadIdx.x;
    if (idx < total) { g_Ahi[idx] = __float2bfloat16(0.f); g_Alo[idx] = __float2bfloat16(0.f); }
}

template<int K>
__global__ void prep_B(const float* __restrict__ Wq, const float* __restrict__ Wk,
                       const float* __restrict__ Wv, const float* __restrict__ Ws,
                       const float* __restrict__ bq, const float* __restrict__ bk,
                       const float* __restrict__ bv, const float* __restrict__ bs) {
    int idx = blockIdx.x * blockDim.x + threadIdx.x;
    if (idx >= 512 * K) return;
    int nglob = idx / K, k = idx % K;
    int w = nglob >> 7, nloc = nglob & 127;
    const float* W; const float* B;
    switch (w) {
        case 0:  W = Wq; B = bq; break;
        case 1:  W = Wk; B = bk; break;
        case 2:  W = Wv; B = bv; break;
        default: W = Ws; B = bs; break;
    }
    float v = W[(size_t)k * Hd + nloc];
    __nv_bfloat16 hi = __float2bfloat16(v);
    __nv_bfloat16 lo = __float2bfloat16(v - __bfloat162float(hi));
    g_Bhi[idx] = hi;   // [n][k], K-contiguous == col-major B for mma
    g_Blo[idx] = lo;
    if (k == 0) g_bias[nglob] = B[nloc];
}

// ---------------- HMMA GEMM: out[tile*128.., chunk*128..] += A @ B^T + bias ----------------
// Block 128(M) x 128(N), BK=32, 8 warps arranged 4(M) x 2(N); warp tile 32x64.
#define SSTR 48   // smem row stride in bf16 (32 data + 16 pad): 96B rows, 16B-aligned, low-conflict

template<int K>
__global__ void __launch_bounds__(256) gemm_mma(int n) {
    __shared__ __nv_bfloat16 sAh[128 * SSTR], sAl[128 * SSTR];
    __shared__ __nv_bfloat16 sBh[128 * SSTR], sBl[128 * SSTR];

    const int tid   = threadIdx.x;
    const int tile  = blockIdx.x;
    const int chunk = blockIdx.y;     // 0..3 -> q|k|v|s
    const int wid   = tid >> 5, lane = tid & 31;
    const int wm    = (wid & 3) * 32;
    const int wn    = (wid >> 2) * 64;
    const int gid   = lane >> 2;      // 0..7
    const int tig   = lane & 3;       // 0..3

    float acc[2][8][4];
    #pragma unroll
    for (int m = 0; m < 2; m++)
        #pragma unroll
        for (int t = 0; t < 8; t++)
            #pragma unroll
            for (int j = 0; j < 4; j++) acc[m][t][j] = 0.f;

    #pragma unroll 1
    for (int kt = 0; kt < K; kt += 32) {
        // stage A/B hi+lo tiles (128 x 32 bf16 each) into SMEM
        #pragma unroll
        for (int i = tid; i < 512; i += 256) {
            int r = i >> 2, kc = (i & 3) * 8;
            size_t ga = (size_t)(tile * 128 + r) * K + kt + kc;
            size_t gb = (size_t)(chunk * 128 + r) * K + kt + kc;
            *(uint4*)&sAh[r * SSTR + kc] = *(const uint4*)(g_Ahi + ga);
            *(uint4*)&sAl[r * SSTR + kc] = *(const uint4*)(g_Alo + ga);
            *(uint4*)&sBh[r * SSTR + kc] = *(const uint4*)(g_Bhi + gb);
            *(uint4*)&sBl[r * SSTR + kc] = *(const uint4*)(g_Blo + gb);
        }
        __syncthreads();

        #pragma unroll
        for (int ks = 0; ks < 2; ks++) {
            const int kb = ks * 16 + tig * 2;
            uint32_t ah[2][4], al[2][4];
            #pragma unroll
            for (int mt = 0; mt < 2; mt++) {
                int r = wm + mt * 16 + gid;
                ah[mt][0] = *(const uint32_t*)&sAh[r * SSTR + kb];
                ah[mt][1] = *(const uint32_t*)&sAh[(r + 8) * SSTR + kb];
                ah[mt][2] = *(const uint32_t*)&sAh[r * SSTR + kb + 8];
                ah[mt][3] = *(const uint32_t*)&sAh[(r + 8) * SSTR + kb + 8];
                al[mt][0] = *(const uint32_t*)&sAl[r * SSTR + kb];
                al[mt][1] = *(const uint32_t*)&sAl[(r + 8) * SSTR + kb];
                al[mt][2] = *(const uint32_t*)&sAl[r * SSTR + kb + 8];
                al[mt][3] = *(const uint32_t*)&sAl[(r + 8) * SSTR + kb + 8];
            }
            #pragma unroll
            for (int nt = 0; nt < 8; nt++) {
                int nr = wn + nt * 8 + gid;
                uint32_t bh0 = *(const uint32_t*)&sBh[nr * SSTR + kb];
                uint32_t bh1 = *(const uint32_t*)&sBh[nr * SSTR + kb + 8];
                uint32_t bl0 = *(const uint32_t*)&sBl[nr * SSTR + kb];
                uint32_t bl1 = *(const uint32_t*)&sBl[nr * SSTR + kb + 8];
                #pragma unroll
                for (int mt = 0; mt < 2; mt++) {
                    mma16816(acc[mt][nt], ah[mt][0], ah[mt][1], ah[mt][2], ah[mt][3], bh0, bh1);
                    mma16816(acc[mt][nt], ah[mt][0], ah[mt][1], ah[mt][2], ah[mt][3], bl0, bl1);
                    mma16816(acc[mt][nt], al[mt][0], al[mt][1], al[mt][2], al[mt][3], bh0, bh1);
                }
            }
        }
        __syncthreads();
    }

    // epilogue: + bias, write fp32 into g_qkvs
    #pragma unroll
    for (int mt = 0; mt < 2; mt++) {
        long row = (long)tile * 128 + wm + mt * 16 + gid;
        #pragma unroll
        for (int nt = 0; nt < 8; nt++) {
            int col = chunk * 128 + wn + nt * 8 + tig * 2;
            float b0 = g_bias[col], b1 = g_bias[col + 1];
            if (row < n) {
                float2 o = make_float2(acc[mt][nt][0] + b0, acc[mt][nt][1] + b1);
                *(float2*)(g_qkvs + row * 512 + col) = o;
            }
            if (row + 8 < n) {
                float2 o = make_float2(acc[mt][nt][2] + b0, acc[mt][nt][3] + b1);
                *(float2*)(g_qkvs + (row + 8) * 512 + col) = o;
            }
        }
    }
}

// ---------------- misc ----------------
__device__ __forceinline__ void atomicMaxFloat(float* addr, float val) {
    int* ia = (int*)addr;
    int old = *ia;
    while (__int_as_float(old) < val) {
        int assumed = old;
        old = atomicCAS(ia, assumed, __float_as_int(val));
        if (old == assumed) break;
    }
}

__global__ void layer_init(int n) {
    long stride = (long)gridDim.x * blockDim.x;
    long idx = (long)blockIdx.x * blockDim.x + threadIdx.x;
    long total = (long)n * Hd;
    for (long i = idx; i < total; i += stride) g_agg[i] = 0.f;
    for (long i = idx; i < n; i += stride) { g_m[i] = -INFINITY; g_sden[i] = 0.f; }
    if (idx < Hd) { g_sum[idx] = 0.0; g_sumsq[idx] = 0.0; }
}

// ---------------- edge attention ----------------
__global__ void attn_score(const int* __restrict__ src, const int* __restrict__ dst, int E) {
    int e = (blockIdx.x * blockDim.x + threadIdx.x) >> 5;
    int lane = threadIdx.x & 31;
    if (e >= E) return;
    int sN = src[e], dN = dst[e];
    float4 q = *(const float4*)(g_qkvs + (size_t)dN * 512 + lane * 4);
    float4 k = *(const float4*)(g_qkvs + (size_t)sN * 512 + Hd + lane * 4);
    float p = q.x * k.x + q.y * k.y + q.z * k.z + q.w * k.w;
    #pragma unroll
    for (int o = 16; o; o >>= 1) p += __shfl_xor_sync(0xffffffffu, p, o);
    if (lane == 0) {
        p *= 0.08838834764831845f;
        g_ea[e] = p;
        atomicMaxFloat(&g_m[dN], p);
    }
}

__global__ void attn_exp(const int* __restrict__ dst, int E) {
    int e = blockIdx.x * blockDim.x + threadIdx.x;
    if (e >= E) return;
    int dN = dst[e];
    float w = expf(g_ea[e] - g_m[dN]);
    g_ea[e] = w;
    atomicAdd(&g_sden[dN], w);
}

__global__ void attn_agg(const int* __restrict__ src, const int* __restrict__ dst, int E) {
    int e = (blockIdx.x * blockDim.x + threadIdx.x) >> 5;
    int lane = threadIdx.x & 31;
    if (e >= E) return;
    int sN = src[e], dN = dst[e];
    float w = g_ea[e] / g_sden[dN];
    float4 v = *(const float4*)(g_qkvs + (size_t)sN * 512 + 2 * Hd + lane * 4);
    float* dp = g_agg + (size_t)dN * Hd + lane * 4;
    atomicAdd(dp + 0, v.x * w);
    atomicAdd(dp + 1, v.y * w);
    atomicAdd(dp + 2, v.z * w);
    atomicAdd(dp + 3, v.w * w);
}

// ---------------- BN ----------------
__global__ void __launch_bounds__(256) bn_pre(int n) {
    int c = threadIdx.x & 127;
    int half = threadIdx.x >> 7;
    double s = 0.0, ss = 0.0;
    for (int i = blockIdx.x * 2 + half; i < n; i += gridDim.x * 2) {
        float v = g_agg[(size_t)i * Hd + c] + g_qkvs[(size_t)i * 512 + 3 * Hd + c];
        g_h[(size_t)i * Hd + c] = v;
        s += v;
        ss += (double)v * (double)v;
    }
    __shared__ double sh[256], sh2[256];
    sh[threadIdx.x] = s; sh2[threadIdx.x] = ss;
    __syncthreads();
    if (half == 0) {
        s  += sh[128 + c];
        ss += sh2[128 + c];
        atomicAdd(&g_sum[c], s);
        atomicAdd(&g_sumsq[c], ss);
    }
}

__global__ void bn_stats(int n, const float* __restrict__ gamma, const float* __restrict__ beta) {
    int c = threadIdx.x;
    if (c >= Hd) return;
    double mean = g_sum[c] / n;
    double var  = g_sumsq[c] / n - mean * mean;
    if (var < 0.0) var = 0.0;
    float inv = (float)rsqrt(var + 1e-5);
    float sc = inv * gamma[c];
    g_scale[c] = sc;
    g_shift[c] = beta[c] - (float)mean * sc;
}

// fused: BN affine + ReLU -> g_h, plus bf16 hi/lo split image for next layer's GEMM (K=128)
__global__ void bn_apply_fused(int n) {
    long stride = (long)gridDim.x * blockDim.x;
    long total = (long)n * Hd;
    for (long i = (long)blockIdx.x * blockDim.x + threadIdx.x; i < total; i += stride) {
        int c = (int)(i & 127);
        float v = fmaxf(g_h[i] * g_scale[c] + g_shift[c], 0.f);
        g_h[i] = v;
        __nv_bfloat16 hi = __float2bfloat16(v);
        __nv_bfloat16 lo = __float2bfloat16(v - __bfloat162float(hi));
        g_Ahi[i] = hi;
        g_Alo[i] = lo;
    }
}

// ---------------- pool + classify ----------------
__global__ void pool_init() {
    int idx = blockIdx.x * blockDim.x + threadIdx.x;
    if (idx < Gg * Hd) g_pool[idx] = 0.f;
    if (idx < Gg) g_cnt[idx] = 0.f;
}

__global__ void pool_accum(const int* __restrict__ batch, int n) {
    long stride = (long)gridDim.x * blockDim.x;
    long total = (long)n * Hd;
    for (long idx = (long)blockIdx.x * blockDim.x + threadIdx.x; idx < total; idx += stride) {
        int i = (int)(idx >> 7);
        int c = (int)(idx & 127);
        int b = batch[i];
        atomicAdd(&g_pool[b * Hd + c], g_h[idx]);
        if (c == 0) atomicAdd(&g_cnt[b], 1.f);
    }
}

__global__ void classify(const float* __restrict__ W, const float* __restrict__ b,
                         float* __restrict__ out) {
    int g = blockIdx.x;
    int c = threadIdx.x;
    if (c >= Cc) return;
    float inv = 1.f / fmaxf(g_cnt[g], 1.f);
    float acc = 0.f;
    #pragma unroll 8
    for (int h = 0; h < Hd; h++) acc += g_pool[g * Hd + h] * W[h * Cc + c];
    out[g * Cc + c] = acc * inv + b[c];
}

// ---------------- host orchestration ----------------
template<int K>
static void run_layer(int n, int ntiles, int E,
                      const int* src, const int* dst,
                      const float* Wq, const float* bq,
                      const float* Wk, const float* bk,
                      const float* Wv, const float* bv,
                      const float* Ws, const float* bs,
                      const float* bng, const float* bnb)
{
    layer_init<<<512, 256>>>(n);
    prep_B<K><<<(512 * K + 255) / 256, 256>>>(Wq, Wk, Wv, Ws, bq, bk, bv, bs);
    gemm_mma<K><<<dim3(ntiles, 4), 256>>>(n);
    long ethreads = (long)E * 32;
    attn_score<<<(unsigned)((ethreads + 255) / 256), 256>>>(src, dst, E);
    attn_exp<<<(E + 255) / 256, 256>>>(dst, E);
    attn_agg<<<(unsigned)((ethreads + 255) / 256), 256>>>(src, dst, E);
    bn_pre<<<256, 256>>>(n);
    bn_stats<<<1, 128>>>(n, bng, bnb);
    bn_apply_fused<<<512, 256>>>(n);
}

extern "C" void kernel_launch(void* const* d_in, const int* in_sizes, int n_in,
                              void* d_out, int out_size)
{
    const float* x     = (const float*)d_in[0];
    const int*   ei    = (const int*)d_in[1];
    const int*   batch = (const int*)d_in[2];
    const float* Wq1 = (const float*)d_in[3];
    const float* bq1 = (const float*)d_in[4];
    const float* Wk1 = (const float*)d_in[5];
    const float* bk1 = (const float*)d_in[6];
    const float* Wv1 = (const float*)d_in[7];
    const float* bv1 = (const float*)d_in[8];
    const float* Ws1 = (const float*)d_in[9];
    const float* bs1 = (const float*)d_in[10];
    const float* bn1g = (const float*)d_in[11];
    const float* bn1b = (const float*)d_in[12];
    const float* Wq = (const float*)d_in[13];
    const float* bq = (const float*)d_in[14];
    const float* Wk = (const float*)d_in[15];
    const float* bk = (const float*)d_in[16];
    const float* Wv = (const float*)d_in[17];
    const float* bv = (const float*)d_in[18];
    const float* Ws = (const float*)d_in[19];
    const float* bs = (const float*)d_in[20];
    const float* bng = (const float*)d_in[21];
    const float* bnb = (const float*)d_in[22];
    const float* linW = (const float*)d_in[23];
    const float* linb = (const float*)d_in[24];

    int n = in_sizes[0] / IN_DIM;
    int E = in_sizes[1] / 2;
    int ntiles = (n + 127) / 128;
    const int* src = ei;
    const int* dst = ei + E;

    // one-time: zero the padded tail rows of the K=128 A-image
    long padElems = (long)ntiles * 128 * Hd - (long)n * Hd;
    if (padElems > 0)
        zero_padA<<<(unsigned)((padElems + 255) / 256), 256>>>(n, ntiles);

    // layer 1: A image from x (K=64)
    long atot = (long)ntiles * 128 * IN_DIM;
    prep_A<IN_DIM><<<(unsigned)((atot + 255) / 256), 256>>>(x, n, ntiles);
    run_layer<IN_DIM>(n, ntiles, E, src, dst,
                      Wq1, bq1, Wk1, bk1, Wv1, bv1, Ws1, bs1, bn1g, bn1b);

    // hidden layers: A image produced by previous bn_apply_fused (K=128)
    for (int i = 0; i < Ld; i++) {
        run_layer<Hd>(n, ntiles, E, src, dst,
                      Wq + (size_t)i * Hd * Hd, bq + i * Hd,
                      Wk + (size_t)i * Hd * Hd, bk + i * Hd,
                      Wv + (size_t)i * Hd * Hd, bv + i * Hd,
                      Ws + (size_t)i * Hd * Hd, bs + i * Hd,
                      bng + i * Hd, bnb + i * Hd);
    }

    pool_init<<<(Gg * Hd + 255) / 256, 256>>>();
    pool_accum<<<1024, 256>>>(batch, n);
    classify<<<Gg, 32>>>(linW, linb, (float*)d_out);
}

// round 4
// speedup vs baseline: 2.1770x; 1.8050x over previous
#include <cuda_runtime.h>
#include <cuda_bf16.h>
#include <math.h>
#include <stdint.h>

// Problem constants
#define Nn 100000
#define Ee 600000
#define IN_DIM 64
#define Hd 128
#define Ld 3
#define Gg 256
#define Cc 10
#define NTILES ((Nn + 127) / 128)

// ---------------- device scratch ----------------
__device__ float  g_h[(size_t)Nn * Hd];
__device__ float  g_qkvs[(size_t)Nn * 4 * Hd];    // [N,512]: q|k|v|s
__device__ double g_sum[Hd];
__device__ double g_sumsq[Hd];
__device__ float  g_scale[Hd];
__device__ float  g_shift[Hd];
__device__ float  g_pool[Gg * Hd];
__device__ float  g_cnt[Gg];
// CSR (built once per launch; edges identical across layers)
__device__ int    g_deg[Nn];          // degree, then reused as scatter cursor
__device__ int    g_off[Nn + 1];
__device__ int    g_bsum[1024];
__device__ int    g_srcSorted[Ee];
// bf16 hi/lo split staging for MMA GEMM (plain K-major layouts)
__device__ __nv_bfloat16 g_Ahi[(size_t)NTILES * 128 * 128];
__device__ __nv_bfloat16 g_Alo[(size_t)NTILES * 128 * 128];
__device__ __nv_bfloat16 g_Bhi[512 * 128];
__device__ __nv_bfloat16 g_Blo[512 * 128];
__device__ float  g_bias[512];

// ---------------- mma.sync helper ----------------
__device__ __forceinline__ void mma16816(float* d,
    uint32_t a0, uint32_t a1, uint32_t a2, uint32_t a3,
    uint32_t b0, uint32_t b1)
{
    asm volatile(
        "mma.sync.aligned.m16n8k16.row.col.f32.bf16.bf16.f32 "
        "{%0,%1,%2,%3}, {%4,%5,%6,%7}, {%8,%9}, {%0,%1,%2,%3};"
        : "+f"(d[0]), "+f"(d[1]), "+f"(d[2]), "+f"(d[3])
        : "r"(a0), "r"(a1), "r"(a2), "r"(a3), "r"(b0), "r"(b1));
}

// ---------------- prep kernels: fp32 -> bf16 hi/lo split ----------------
template<int K>
__global__ void prep_A(const float* __restrict__ src, int n, int ntiles) {
    long total = (long)ntiles * 128 * K;
    long idx = (long)blockIdx.x * blockDim.x + threadIdx.x;
    if (idx >= total) return;
    long i = idx / K;
    int  k = (int)(idx % K);
    float v = (i < n) ? src[i * K + k] : 0.f;
    __nv_bfloat16 hi = __float2bfloat16(v);
    __nv_bfloat16 lo = __float2bfloat16(v - __bfloat162float(hi));
    g_Ahi[idx] = hi;
    g_Alo[idx] = lo;
}

__global__ void zero_padA(int n, int ntiles) {
    long start = (long)n * Hd;
    long total = (long)ntiles * 128 * Hd;
    long idx = start + (long)blockIdx.x * blockDim.x + threadIdx.x;
    if (idx < total) { g_Ahi[idx] = __float2bfloat16(0.f); g_Alo[idx] = __float2bfloat16(0.f); }
}

template<int K>
__global__ void prep_B(const float* __restrict__ Wq, const float* __restrict__ Wk,
                       const float* __restrict__ Wv, const float* __restrict__ Ws,
                       const float* __restrict__ bq, const float* __restrict__ bk,
                       const float* __restrict__ bv, const float* __restrict__ bs) {
    int idx = blockIdx.x * blockDim.x + threadIdx.x;
    if (idx >= 512 * K) return;
    int nglob = idx / K, k = idx % K;
    int w = nglob >> 7, nloc = nglob & 127;
    const float* W; const float* B;
    switch (w) {
        case 0:  W = Wq; B = bq; break;
        case 1:  W = Wk; B = bk; break;
        case 2:  W = Wv; B = bv; break;
        default: W = Ws; B = bs; break;
    }
    float v = W[(size_t)k * Hd + nloc];
    __nv_bfloat16 hi = __float2bfloat16(v);
    __nv_bfloat16 lo = __float2bfloat16(v - __bfloat162float(hi));
    g_Bhi[idx] = hi;
    g_Blo[idx] = lo;
    if (k == 0) g_bias[nglob] = B[nloc];
}

// ---------------- HMMA GEMM ----------------
#define SSTR 48

template<int K>
__global__ void __launch_bounds__(256) gemm_mma(int n) {
    __shared__ __nv_bfloat16 sAh[128 * SSTR], sAl[128 * SSTR];
    __shared__ __nv_bfloat16 sBh[128 * SSTR], sBl[128 * SSTR];

    const int tid   = threadIdx.x;
    const int tile  = blockIdx.x;
    const int chunk = blockIdx.y;
    const int wid   = tid >> 5, lane = tid & 31;
    const int wm    = (wid & 3) * 32;
    const int wn    = (wid >> 2) * 64;
    const int gid   = lane >> 2;
    const int tig   = lane & 3;

    float acc[2][8][4];
    #pragma unroll
    for (int m = 0; m < 2; m++)
        #pragma unroll
        for (int t = 0; t < 8; t++)
            #pragma unroll
            for (int j = 0; j < 4; j++) acc[m][t][j] = 0.f;

    #pragma unroll 1
    for (int kt = 0; kt < K; kt += 32) {
        #pragma unroll
        for (int i = tid; i < 512; i += 256) {
            int r = i >> 2, kc = (i & 3) * 8;
            size_t ga = (size_t)(tile * 128 + r) * K + kt + kc;
            size_t gb = (size_t)(chunk * 128 + r) * K + kt + kc;
            *(uint4*)&sAh[r * SSTR + kc] = *(const uint4*)(g_Ahi + ga);
            *(uint4*)&sAl[r * SSTR + kc] = *(const uint4*)(g_Alo + ga);
            *(uint4*)&sBh[r * SSTR + kc] = *(const uint4*)(g_Bhi + gb);
            *(uint4*)&sBl[r * SSTR + kc] = *(const uint4*)(g_Blo + gb);
        }
        __syncthreads();

        #pragma unroll
        for (int ks = 0; ks < 2; ks++) {
            const int kb = ks * 16 + tig * 2;
            uint32_t ah[2][4], al[2][4];
            #pragma unroll
            for (int mt = 0; mt < 2; mt++) {
                int r = wm + mt * 16 + gid;
                ah[mt][0] = *(const uint32_t*)&sAh[r * SSTR + kb];
                ah[mt][1] = *(const uint32_t*)&sAh[(r + 8) * SSTR + kb];
                ah[mt][2] = *(const uint32_t*)&sAh[r * SSTR + kb + 8];
                ah[mt][3] = *(const uint32_t*)&sAh[(r + 8) * SSTR + kb + 8];
                al[mt][0] = *(const uint32_t*)&sAl[r * SSTR + kb];
                al[mt][1] = *(const uint32_t*)&sAl[(r + 8) * SSTR + kb];
                al[mt][2] = *(const uint32_t*)&sAl[r * SSTR + kb + 8];
                al[mt][3] = *(const uint32_t*)&sAl[(r + 8) * SSTR + kb + 8];
            }
            #pragma unroll
            for (int nt = 0; nt < 8; nt++) {
                int nr = wn + nt * 8 + gid;
                uint32_t bh0 = *(const uint32_t*)&sBh[nr * SSTR + kb];
                uint32_t bh1 = *(const uint32_t*)&sBh[nr * SSTR + kb + 8];
                uint32_t bl0 = *(const uint32_t*)&sBl[nr * SSTR + kb];
                uint32_t bl1 = *(const uint32_t*)&sBl[nr * SSTR + kb + 8];
                #pragma unroll
                for (int mt = 0; mt < 2; mt++) {
                    mma16816(acc[mt][nt], ah[mt][0], ah[mt][1], ah[mt][2], ah[mt][3], bh0, bh1);
                    mma16816(acc[mt][nt], ah[mt][0], ah[mt][1], ah[mt][2], ah[mt][3], bl0, bl1);
                    mma16816(acc[mt][nt], al[mt][0], al[mt][1], al[mt][2], al[mt][3], bh0, bh1);
                }
            }
        }
        __syncthreads();
    }

    #pragma unroll
    for (int mt = 0; mt < 2; mt++) {
        long row = (long)tile * 128 + wm + mt * 16 + gid;
        #pragma unroll
        for (int nt = 0; nt < 8; nt++) {
            int col = chunk * 128 + wn + nt * 8 + tig * 2;
            float b0 = g_bias[col], b1 = g_bias[col + 1];
            if (row < n) {
                float2 o = make_float2(acc[mt][nt][0] + b0, acc[mt][nt][1] + b1);
                *(float2*)(g_qkvs + row * 512 + col) = o;
            }
            if (row + 8 < n) {
                float2 o = make_float2(acc[mt][nt][2] + b0, acc[mt][nt][3] + b1);
                *(float2*)(g_qkvs + (row + 8) * 512 + col) = o;
            }
        }
    }
}

// ---------------- CSR build (once per launch) ----------------
__global__ void csr_zero(int n) {
    int i = blockIdx.x * blockDim.x + threadIdx.x;
    if (i < n) g_deg[i] = 0;
    if (i == 0) g_off[0] = 0;
    if (i < Hd) { g_sum[i] = 0.0; g_sumsq[i] = 0.0; }  // also pre-zero BN accums for layer 1
}

__global__ void csr_count(const int* __restrict__ dst, int E) {
    int e = blockIdx.x * blockDim.x + threadIdx.x;
    if (e < E) atomicAdd(&g_deg[dst[e]], 1);
}

__global__ void scan1(int n) {
    __shared__ int sh[1024];
    int t = threadIdx.x;
    int i = blockIdx.x * 1024 + t;
    int x = (i < n) ? g_deg[i] : 0;
    sh[t] = x;
    __syncthreads();
    #pragma unroll
    for (int d = 1; d < 1024; d <<= 1) {
        int v = (t >= d) ? sh[t - d] : 0;
        __syncthreads();
        sh[t] += v;
        __syncthreads();
    }
    if (i < n) g_off[i + 1] = sh[t];
    if (t == 1023) g_bsum[blockIdx.x] = sh[t];
}

__global__ void scan2(int nb) {
    __shared__ int sh[1024];
    int t = threadIdx.x;
    int v = (t < nb) ? g_bsum[t] : 0;
    sh[t] = v;
    __syncthreads();
    #pragma unroll
    for (int d = 1; d < 1024; d <<= 1) {
        int u = (t >= d) ? sh[t - d] : 0;
        __syncthreads();
        sh[t] += u;
        __syncthreads();
    }
    int ex = (t == 0) ? 0 : sh[t - 1];
    if (t < nb) g_bsum[t] = ex;
}

__global__ void scan3(int n) {
    int i = blockIdx.x * blockDim.x + threadIdx.x;
    if (i < n) g_off[i + 1] += g_bsum[i >> 10];
}

__global__ void csr_cursor(int n) {
    int i = blockIdx.x * blockDim.x + threadIdx.x;
    if (i < n) g_deg[i] = g_off[i];
}

__global__ void csr_scatter(const int* __restrict__ src, const int* __restrict__ dst, int E) {
    int e = blockIdx.x * blockDim.x + threadIdx.x;
    if (e >= E) return;
    int pos = atomicAdd(&g_deg[dst[e]], 1);
    g_srcSorted[pos] = src[e];
}

// ---------------- fused attention: online softmax + skip + BN stats ----------------
__global__ void __launch_bounds__(256) attn_fused(int n) {
    __shared__ float ssum[Hd], ssq[Hd];
    for (int i = threadIdx.x; i < Hd; i += 256) { ssum[i] = 0.f; ssq[i] = 0.f; }
    __syncthreads();

    const int lane = threadIdx.x & 31;
    const int c0 = lane * 4;
    const int wstride = gridDim.x * 8;
    float ls0 = 0.f, ls1 = 0.f, ls2 = 0.f, ls3 = 0.f;
    float lq0 = 0.f, lq1 = 0.f, lq2 = 0.f, lq3 = 0.f;

    for (int node = blockIdx.x * 8 + (threadIdx.x >> 5); node < n; node += wstride) {
        const int off0 = g_off[node];
        const int deg  = g_off[node + 1] - off0;
        const float4 q = *(const float4*)(g_qkvs + (size_t)node * 512 + c0);

        float m = -INFINITY, sum = 0.f;
        float ax = 0.f, ay = 0.f, az = 0.f, aw = 0.f;
        for (int j = 0; j < deg; j++) {
            int s = g_srcSorted[off0 + j];
            const float* row = g_qkvs + (size_t)s * 512;
            float4 kk = *(const float4*)(row + 128 + c0);
            float p = q.x * kk.x + q.y * kk.y + q.z * kk.z + q.w * kk.w;
            #pragma unroll
            for (int o = 16; o; o >>= 1) p += __shfl_xor_sync(0xffffffffu, p, o);
            p *= 0.08838834764831845f;
            float mn = fmaxf(m, p);
            float r = expf(m - mn);
            float w = expf(p - mn);
            float4 vv = *(const float4*)(row + 256 + c0);
            ax = ax * r + w * vv.x;
            ay = ay * r + w * vv.y;
            az = az * r + w * vv.z;
            aw = aw * r + w * vv.w;
            sum = sum * r + w;
            m = mn;
        }
        float inv = (deg > 0) ? 1.f / sum : 0.f;
        float4 sk = *(const float4*)(g_qkvs + (size_t)node * 512 + 384 + c0);
        float h0 = ax * inv + sk.x;
        float h1 = ay * inv + sk.y;
        float h2 = az * inv + sk.z;
        float h3 = aw * inv + sk.w;
        *(float4*)(g_h + (size_t)node * Hd + c0) = make_float4(h0, h1, h2, h3);
        ls0 += h0; ls1 += h1; ls2 += h2; ls3 += h3;
        lq0 += h0 * h0; lq1 += h1 * h1; lq2 += h2 * h2; lq3 += h3 * h3;
    }

    atomicAdd(&ssum[c0 + 0], ls0); atomicAdd(&ssq[c0 + 0], lq0);
    atomicAdd(&ssum[c0 + 1], ls1); atomicAdd(&ssq[c0 + 1], lq1);
    atomicAdd(&ssum[c0 + 2], ls2); atomicAdd(&ssq[c0 + 2], lq2);
    atomicAdd(&ssum[c0 + 3], ls3); atomicAdd(&ssq[c0 + 3], lq3);
    __syncthreads();
    if (threadIdx.x < Hd) {
        atomicAdd(&g_sum[threadIdx.x], (double)ssum[threadIdx.x]);
        atomicAdd(&g_sumsq[threadIdx.x], (double)ssq[threadIdx.x]);
    }
}

// ---------------- BN stats -> folded scale/shift; also re-zero accums for next layer ----------------
__global__ void bn_stats(int n, const float* __restrict__ gamma, const float* __restrict__ beta) {
    int c = threadIdx.x;
    if (c >= Hd) return;
    double mean = g_sum[c] / n;
    double var  = g_sumsq[c] / n - mean * mean;
    if (var < 0.0) var = 0.0;
    float inv = (float)rsqrt(var + 1e-5);
    float sc = inv * gamma[c];
    g_scale[c] = sc;
    g_shift[c] = beta[c] - (float)mean * sc;
    g_sum[c] = 0.0;
    g_sumsq[c] = 0.0;
}

// BN affine + ReLU; mid layers: emit bf16 hi/lo A image; last layer: pool directly
__global__ void bn_apply_fused(int n, const int* __restrict__ batch, int last) {
    long stride = (long)gridDim.x * blockDim.x;
    long total = (long)n * Hd;
    for (long i = (long)blockIdx.x * blockDim.x + threadIdx.x; i < total; i += stride) {
        int c = (int)(i & 127);
        float v = fmaxf(g_h[i] * g_scale[c] + g_shift[c], 0.f);
        if (!last) {
            g_h[i] = v;
            __nv_bfloat16 hi = __float2bfloat16(v);
            __nv_bfloat16 lo = __float2bfloat16(v - __bfloat162float(hi));
            g_Ahi[i] = hi;
            g_Alo[i] = lo;
        } else {
            int node = (int)(i >> 7);
            atomicAdd(&g_pool[batch[node] * Hd + c], v);
        }
    }
}

// ---------------- pool + classify ----------------
__global__ void pool_init() {
    int idx = blockIdx.x * blockDim.x + threadIdx.x;
    if (idx < Gg * Hd) g_pool[idx] = 0.f;
}

__global__ void graph_counts(const int* __restrict__ batch, int n) {
    int g = threadIdx.x;
    if (g >= Gg) return;
    int lo = 0, hi = n;
    while (lo < hi) { int mid = (lo + hi) >> 1; if (batch[mid] < g) lo = mid + 1; else hi = mid; }
    int lb = lo;
    lo = 0; hi = n;
    while (lo < hi) { int mid = (lo + hi) >> 1; if (batch[mid] <= g) lo = mid + 1; else hi = mid; }
    g_cnt[g] = (float)(lo - lb);
}

__global__ void classify(const float* __restrict__ W, const float* __restrict__ b,
                         float* __restrict__ out) {
    int g = blockIdx.x;
    int c = threadIdx.x;
    if (c >= Cc) return;
    float inv = 1.f / fmaxf(g_cnt[g], 1.f);
    float acc = 0.f;
    #pragma unroll 8
    for (int h = 0; h < Hd; h++) acc += g_pool[g * Hd + h] * W[h * Cc + c];
    out[g * Cc + c] = acc * inv + b[c];
}

// ---------------- host orchestration ----------------
template<int K>
static void run_layer(int n, int ntiles, const int* batch, int last,
                      const float* Wq, const float* bq,
                      const float* Wk, const float* bk,
                      const float* Wv, const float* bv,
                      const float* Ws, const float* bs,
                      const float* bng, const float* bnb)
{
    prep_B<K><<<(512 * K + 255) / 256, 256>>>(Wq, Wk, Wv, Ws, bq, bk, bv, bs);
    gemm_mma<K><<<dim3(ntiles, 4), 256>>>(n);
    attn_fused<<<2048, 256>>>(n);
    bn_stats<<<1, 128>>>(n, bng, bnb);
    bn_apply_fused<<<512, 256>>>(n, batch, last);
}

extern "C" void kernel_launch(void* const* d_in, const int* in_sizes, int n_in,
                              void* d_out, int out_size)
{
    const float* x     = (const float*)d_in[0];
    const int*   ei    = (const int*)d_in[1];
    const int*   batch = (const int*)d_in[2];
    const float* Wq1 = (const float*)d_in[3];
    const float* bq1 = (const float*)d_in[4];
    const float* Wk1 = (const float*)d_in[5];
    const float* bk1 = (const float*)d_in[6];
    const float* Wv1 = (const float*)d_in[7];
    const float* bv1 = (const float*)d_in[8];
    const float* Ws1 = (const float*)d_in[9];
    const float* bs1 = (const float*)d_in[10];
    const float* bn1g = (const float*)d_in[11];
    const float* bn1b = (const float*)d_in[12];
    const float* Wq = (const float*)d_in[13];
    const float* bq = (const float*)d_in[14];
    const float* Wk = (const float*)d_in[15];
    const float* bk = (const float*)d_in[16];
    const float* Wv = (const float*)d_in[17];
    const float* bv = (const float*)d_in[18];
    const float* Ws = (const float*)d_in[19];
    const float* bs = (const float*)d_in[20];
    const float* bng = (const float*)d_in[21];
    const float* bnb = (const float*)d_in[22];
    const float* linW = (const float*)d_in[23];
    const float* linb = (const float*)d_in[24];

    int n = in_sizes[0] / IN_DIM;
    int E = in_sizes[1] / 2;
    int ntiles = (n + 127) / 128;
    const int* src = ei;
    const int* dst = ei + E;

    // ---- one-time setup ----
    // CSR build
    csr_zero<<<(n + 255) / 256, 256>>>(n);
    csr_count<<<(E + 255) / 256, 256>>>(dst, E);
    int nb = (n + 1023) / 1024;
    scan1<<<nb, 1024>>>(n);
    scan2<<<1, 1024>>>(nb);
    scan3<<<(n + 255) / 256, 256>>>(n);
    csr_cursor<<<(n + 255) / 256, 256>>>(n);
    csr_scatter<<<(E + 255) / 256, 256>>>(src, dst, E);
    // pool init + graph counts
    pool_init<<<(Gg * Hd + 255) / 256, 256>>>();
    graph_counts<<<1, 256>>>(batch, n);
    // zero padded tail rows of A image
    long padElems = (long)ntiles * 128 * Hd - (long)n * Hd;
    if (padElems > 0)
        zero_padA<<<(unsigned)((padElems + 255) / 256), 256>>>(n, ntiles);

    // layer 1: A image from x (K=64)
    long atot = (long)ntiles * 128 * IN_DIM;
    prep_A<IN_DIM><<<(unsigned)((atot + 255) / 256), 256>>>(x, n, ntiles);
    run_layer<IN_DIM>(n, ntiles, batch, 0,
                      Wq1, bq1, Wk1, bk1, Wv1, bv1, Ws1, bs1, bn1g, bn1b);

    // hidden layers (K=128); A image produced by previous bn_apply_fused
    for (int i = 0; i < Ld; i++) {
        run_layer<Hd>(n, ntiles, batch, (i == Ld - 1) ? 1 : 0,
                      Wq + (size_t)i * Hd * Hd, bq + i * Hd,
                      Wk + (size_t)i * Hd * Hd, bk + i * Hd,
                      Wv + (size_t)i * Hd * Hd, bv + i * Hd,
                      Ws + (size_t)i * Hd * Hd, bs + i * Hd,
                      bng + i * Hd, bnb + i * Hd);
    }

    classify<<<Gg, 32>>>(linW, linb, (float*)d_out);
}

// round 5
// speedup vs baseline: 2.3219x; 1.0666x over previous
#include <cuda_runtime.h>
#include <cuda_bf16.h>
#include <math.h>
#include <stdint.h>

// Problem constants
#define Nn 100000
#define Ee 600000
#define IN_DIM 64
#define Hd 128
#define Ld 3
#define Gg 256
#define Cc 10
#define NTILES ((Nn + 127) / 128)

// ---------------- device scratch ----------------
__device__ float  g_h[(size_t)Nn * Hd];
__device__ float  g_qkvs[(size_t)Nn * 4 * Hd];    // [N,512]: q|k|v|s
__device__ double g_sum[Hd];
__device__ double g_sumsq[Hd];
__device__ float  g_scale[Hd];
__device__ float  g_shift[Hd];
__device__ float  g_pool[Gg * Hd];
__device__ float  g_cnt[Gg];
// CSR (built once per launch)
__device__ int    g_deg[Nn];
__device__ int    g_off[Nn + 1];
__device__ int    g_srcSorted[Ee];
// bf16 hi/lo split staging (K-major), 16B-aligned for cp.async
__device__ __align__(16) __nv_bfloat16 g_Ahi[(size_t)NTILES * 128 * 128];
__device__ __align__(16) __nv_bfloat16 g_Alo[(size_t)NTILES * 128 * 128];
__device__ __align__(16) __nv_bfloat16 g_Bhi[512 * 128];
__device__ __align__(16) __nv_bfloat16 g_Blo[512 * 128];
__device__ float  g_bias[512];

// ---------------- asm helpers ----------------
__device__ __forceinline__ uint32_t smem_u32(const void* p) {
    uint32_t a;
    asm("{ .reg .u64 t; cvta.to.shared.u64 t, %1; cvt.u32.u64 %0, t; }" : "=r"(a) : "l"(p));
    return a;
}

__device__ __forceinline__ void mma16816(float* d,
    uint32_t a0, uint32_t a1, uint32_t a2, uint32_t a3,
    uint32_t b0, uint32_t b1)
{
    asm volatile(
        "mma.sync.aligned.m16n8k16.row.col.f32.bf16.bf16.f32 "
        "{%0,%1,%2,%3}, {%4,%5,%6,%7}, {%8,%9}, {%0,%1,%2,%3};"
        : "+f"(d[0]), "+f"(d[1]), "+f"(d[2]), "+f"(d[3])
        : "r"(a0), "r"(a1), "r"(a2), "r"(a3), "r"(b0), "r"(b1));
}

__device__ __forceinline__ void ldsm4(uint32_t* r, uint32_t addr) {
    asm volatile("ldmatrix.sync.aligned.m8n8.x4.shared.b16 {%0,%1,%2,%3}, [%4];"
        : "=r"(r[0]), "=r"(r[1]), "=r"(r[2]), "=r"(r[3]) : "r"(addr));
}

#define CP_ASYNC16(dst, src) \
    asm volatile("cp.async.cg.shared.global [%0], [%1], 16;" :: "r"(dst), "l"(src))
#define CP_COMMIT()  asm volatile("cp.async.commit_group;" ::: "memory")
#define CP_WAIT0()   asm volatile("cp.async.wait_group 0;" ::: "memory")

// ---------------- fused layer-1 prep: A split + pad, B split, bias ----------------
__global__ void prep_layer1(const float* __restrict__ x, int n, int ntiles,
                            const float* __restrict__ Wq, const float* __restrict__ Wk,
                            const float* __restrict__ Wv, const float* __restrict__ Ws,
                            const float* __restrict__ bq, const float* __restrict__ bk,
                            const float* __restrict__ bv, const float* __restrict__ bs)
{
    long aTot = (long)ntiles * 128 * IN_DIM;
    long bTot = 512 * IN_DIM;
    long total = aTot + bTot + 512;
    long stride = (long)gridDim.x * blockDim.x;
    for (long idx = (long)blockIdx.x * blockDim.x + threadIdx.x; idx < total; idx += stride) {
        if (idx < aTot) {
            long row = idx / IN_DIM;
            int  k = (int)(idx % IN_DIM);
            float v = (row < n) ? x[row * IN_DIM + k] : 0.f;
            __nv_bfloat16 hi = __float2bfloat16(v);
            g_Ahi[idx] = hi;
            g_Alo[idx] = __float2bfloat16(v - __bfloat162float(hi));
        } else if (idx < aTot + bTot) {
            int j = (int)(idx - aTot);
            int nglob = j / IN_DIM, k = j % IN_DIM;
            int w = nglob >> 7, nloc = nglob & 127;
            const float* W = (w == 0) ? Wq : (w == 1) ? Wk : (w == 2) ? Wv : Ws;
            float v = W[(size_t)k * Hd + nloc];
            __nv_bfloat16 hi = __float2bfloat16(v);
            g_Bhi[j] = hi;
            g_Blo[j] = __float2bfloat16(v - __bfloat162float(hi));
        } else {
            int nglob = (int)(idx - aTot - bTot);
            int w = nglob >> 7, nloc = nglob & 127;
            const float* B = (w == 0) ? bq : (w == 1) ? bk : (w == 2) ? bv : bs;
            g_bias[nglob] = B[nloc];
        }
    }
}

// ---------------- per-layer B prep (hidden layers, K=128) ----------------
__global__ void prep_B128(const float* __restrict__ Wq, const float* __restrict__ Wk,
                          const float* __restrict__ Wv, const float* __restrict__ Ws,
                          const float* __restrict__ bq, const float* __restrict__ bk,
                          const float* __restrict__ bv, const float* __restrict__ bs) {
    int idx = blockIdx.x * blockDim.x + threadIdx.x;
    if (idx >= 512 * Hd) return;
    int nglob = idx / Hd, k = idx % Hd;
    int w = nglob >> 7, nloc = nglob & 127;
    const float* W = (w == 0) ? Wq : (w == 1) ? Wk : (w == 2) ? Wv : Ws;
    float v = W[(size_t)k * Hd + nloc];
    __nv_bfloat16 hi = __float2bfloat16(v);
    g_Bhi[idx] = hi;
    g_Blo[idx] = __float2bfloat16(v - __bfloat162float(hi));
    if (k == 0) {
        const float* B = (w == 0) ? bq : (w == 1) ? bk : (w == 2) ? bv : bs;
        g_bias[nglob] = B[nloc];
    }
}

// ---------------- HMMA GEMM v2: cp.async double-buffer + ldmatrix ----------------
#define SST 40                 // smem row stride (bf16): 80B rows, conflict-free ldmatrix
#define TSZ (128 * SST)        // tile elems

template<int K>
__global__ void __launch_bounds__(256, 2) gemm_mma(int n) {
    extern __shared__ __nv_bfloat16 sm[];
    const int tid = threadIdx.x;
    const int tile = blockIdx.x, chunk = blockIdx.y;
    const int wid = tid >> 5, lane = tid & 31;
    const int wm = (wid & 3) * 32, wn = (wid >> 2) * 64;
    const int gid = lane >> 2, tig = lane & 3;
    const uint32_t smb = smem_u32(sm);
    constexpr int NK = K / 32;

    float acc[2][8][4] = {};

    const __nv_bfloat16* aH = g_Ahi + (size_t)tile * 128 * K;
    const __nv_bfloat16* aL = g_Alo + (size_t)tile * 128 * K;
    const __nv_bfloat16* bH = g_Bhi + (size_t)chunk * 128 * K;
    const __nv_bfloat16* bL = g_Blo + (size_t)chunk * 128 * K;

    auto stage = [&](int buf, int kt) {
        #pragma unroll
        for (int t = 0; t < 8; t++) {
            int idx = tid + t * 256;            // 2048 chunks of 16B
            int tl  = idx >> 9;
            int rem = idx & 511;
            int r = rem >> 2, c = rem & 3;
            const __nv_bfloat16* sp = (tl == 0) ? aH : (tl == 1) ? aL : (tl == 2) ? bH : bL;
            sp += (size_t)r * K + kt + c * 8;
            uint32_t d = smb + (uint32_t)(buf * 4 * TSZ + tl * TSZ + r * SST + c * 8) * 2;
            CP_ASYNC16(d, sp);
        }
        CP_COMMIT();
    };

    stage(0, 0);
    #pragma unroll 1
    for (int it = 0; it < NK; it++) {
        CP_WAIT0();
        __syncthreads();
        if (it + 1 < NK) stage((it + 1) & 1, (it + 1) * 32);

        const uint32_t base = smb + (uint32_t)((it & 1) * 4 * TSZ) * 2;
        #pragma unroll
        for (int ks = 0; ks < 2; ks++) {
            const int kb = ks * 16;
            uint32_t ah[2][4], al[2][4];
            #pragma unroll
            for (int mt = 0; mt < 2; mt++) {
                int row = wm + mt * 16 + (lane & 15);
                int col = kb + ((lane & 16) ? 8 : 0);
                uint32_t ad = base + (uint32_t)(row * SST + col) * 2;
                ldsm4(ah[mt], ad);
                ldsm4(al[mt], ad + TSZ * 2);
            }
            #pragma unroll
            for (int ntp = 0; ntp < 4; ntp++) {
                int row = wn + ntp * 16 + (lane & 7) + ((lane & 16) ? 8 : 0);
                int col = kb + ((lane & 8) ? 8 : 0);
                uint32_t bd = base + (uint32_t)(2 * TSZ + row * SST + col) * 2;
                uint32_t bh[4], bl[4];
                ldsm4(bh, bd);
                ldsm4(bl, bd + TSZ * 2);
                #pragma unroll
                for (int sub = 0; sub < 2; sub++) {
                    int nt = ntp * 2 + sub;
                    #pragma unroll
                    for (int mt = 0; mt < 2; mt++) {
                        mma16816(acc[mt][nt], ah[mt][0], ah[mt][1], ah[mt][2], ah[mt][3], bh[sub*2], bh[sub*2+1]);
                        mma16816(acc[mt][nt], ah[mt][0], ah[mt][1], ah[mt][2], ah[mt][3], bl[sub*2], bl[sub*2+1]);
                        mma16816(acc[mt][nt], al[mt][0], al[mt][1], al[mt][2], al[mt][3], bh[sub*2], bh[sub*2+1]);
                    }
                }
            }
        }
        __syncthreads();
    }

    #pragma unroll
    for (int mt = 0; mt < 2; mt++) {
        long row = (long)tile * 128 + wm + mt * 16 + gid;
        #pragma unroll
        for (int nt = 0; nt < 8; nt++) {
            int col = chunk * 128 + wn + nt * 8 + tig * 2;
            float b0 = g_bias[col], b1 = g_bias[col + 1];
            if (row < n) {
                float2 o = make_float2(acc[mt][nt][0] + b0, acc[mt][nt][1] + b1);
                *(float2*)(g_qkvs + row * 512 + col) = o;
            }
            if (row + 8 < n) {
                float2 o = make_float2(acc[mt][nt][2] + b0, acc[mt][nt][3] + b1);
                *(float2*)(g_qkvs + (row + 8) * 512 + col) = o;
            }
        }
    }
}

// ---------------- setup: zero deg/sums/pool, graph counts, pad A image ----------------
__global__ void setup_init(const int* __restrict__ batch, int n, int ntiles) {
    int idx = blockIdx.x * blockDim.x + threadIdx.x;
    if (idx < n) g_deg[idx] = 0;
    if (idx == 0) g_off[0] = 0;
    if (idx < Hd) { g_sum[idx] = 0.0; g_sumsq[idx] = 0.0; }
    if (idx < Gg * Hd) g_pool[idx] = 0.f;
    if (idx < Gg) {
        int g = idx;
        int lo = 0, hi = n;
        while (lo < hi) { int mid = (lo + hi) >> 1; if (batch[mid] < g) lo = mid + 1; else hi = mid; }
        int lb = lo;
        lo = 0; hi = n;
        while (lo < hi) { int mid = (lo + hi) >> 1; if (batch[mid] <= g) lo = mid + 1; else hi = mid; }
        g_cnt[g] = (float)(lo - lb);
    }
    long pad0 = (long)n * Hd;
    long padN = (long)ntiles * 128 * Hd - pad0;
    if (idx < padN) {
        g_Ahi[pad0 + idx] = __float2bfloat16(0.f);
        g_Alo[pad0 + idx] = __float2bfloat16(0.f);
    }
}

__global__ void csr_count(const int* __restrict__ dst, int E) {
    int e = blockIdx.x * blockDim.x + threadIdx.x;
    if (e < E) atomicAdd(&g_deg[e < E ? dst[e] : 0], 1);
}

// single-block full scan: g_off (exclusive offsets) + g_deg -> cursor copy
__global__ void __launch_bounds__(1024) scan_block(int n) {
    __shared__ int sh[1024];
    int t = threadIdx.x;
    int chunk = (n + 1023) >> 10;
    int s0 = min(t * chunk, n), s1 = min(s0 + chunk, n);
    int s = 0;
    for (int i = s0; i < s1; i++) s += g_deg[i];
    sh[t] = s;
    __syncthreads();
    #pragma unroll
    for (int d = 1; d < 1024; d <<= 1) {
        int v = (t >= d) ? sh[t - d] : 0;
        __syncthreads();
        sh[t] += v;
        __syncthreads();
    }
    int run = (t == 0) ? 0 : sh[t - 1];
    for (int i = s0; i < s1; i++) {
        int d = g_deg[i];
        g_deg[i] = run;          // scatter cursor = offset
        run += d;
        g_off[i + 1] = run;
    }
}

__global__ void csr_scatter(const int* __restrict__ src, const int* __restrict__ dst, int E) {
    int e = blockIdx.x * blockDim.x + threadIdx.x;
    if (e >= E) return;
    int pos = atomicAdd(&g_deg[dst[e]], 1);
    g_srcSorted[pos] = src[e];
}

// ---------------- fused attention: online softmax + skip + BN stats (prefetch d2) ----------------
__global__ void __launch_bounds__(256) attn_fused(int n) {
    __shared__ float ssum[Hd], ssq[Hd];
    for (int i = threadIdx.x; i < Hd; i += 256) { ssum[i] = 0.f; ssq[i] = 0.f; }
    __syncthreads();

    const int lane = threadIdx.x & 31;
    const int c0 = lane * 4;
    const int wstride = gridDim.x * 8;
    float ls0 = 0.f, ls1 = 0.f, ls2 = 0.f, ls3 = 0.f;
    float lq0 = 0.f, lq1 = 0.f, lq2 = 0.f, lq3 = 0.f;

    for (int node = blockIdx.x * 8 + (threadIdx.x >> 5); node < n; node += wstride) {
        const int off0 = g_off[node];
        const int deg  = g_off[node + 1] - off0;
        const float4 q = *(const float4*)(g_qkvs + (size_t)node * 512 + c0);

        float m = -INFINITY, sum = 0.f;
        float ax = 0.f, ay = 0.f, az = 0.f, aw = 0.f;

        float4 kc = make_float4(0,0,0,0), vc = kc, kn = kc, vn = kc;
        if (deg > 0) {
            const float* r0 = g_qkvs + (size_t)g_srcSorted[off0] * 512;
            kc = *(const float4*)(r0 + 128 + c0);
            vc = *(const float4*)(r0 + 256 + c0);
        }
        if (deg > 1) {
            const float* r1 = g_qkvs + (size_t)g_srcSorted[off0 + 1] * 512;
            kn = *(const float4*)(r1 + 128 + c0);
            vn = *(const float4*)(r1 + 256 + c0);
        }
        #pragma unroll 2
        for (int j = 0; j < deg; j++) {
            float4 kk = kc, vv = vc;
            kc = kn; vc = vn;
            if (j + 2 < deg) {
                const float* r2 = g_qkvs + (size_t)g_srcSorted[off0 + j + 2] * 512;
                kn = *(const float4*)(r2 + 128 + c0);
                vn = *(const float4*)(r2 + 256 + c0);
            }
            float p = q.x * kk.x + q.y * kk.y + q.z * kk.z + q.w * kk.w;
            #pragma unroll
            for (int o = 16; o; o >>= 1) p += __shfl_xor_sync(0xffffffffu, p, o);
            p *= 0.08838834764831845f;
            float mn = fmaxf(m, p);
            float r = expf(m - mn);
            float w = expf(p - mn);
            ax = ax * r + w * vv.x;
            ay = ay * r + w * vv.y;
            az = az * r + w * vv.z;
            aw = aw * r + w * vv.w;
            sum = sum * r + w;
            m = mn;
        }
        float inv = (deg > 0) ? 1.f / sum : 0.f;
        float4 sk = *(const float4*)(g_qkvs + (size_t)node * 512 + 384 + c0);
        float h0 = ax * inv + sk.x;
        float h1 = ay * inv + sk.y;
        float h2 = az * inv + sk.z;
        float h3 = aw * inv + sk.w;
        *(float4*)(g_h + (size_t)node * Hd + c0) = make_float4(h0, h1, h2, h3);
        ls0 += h0; ls1 += h1; ls2 += h2; ls3 += h3;
        lq0 += h0 * h0; lq1 += h1 * h1; lq2 += h2 * h2; lq3 += h3 * h3;
    }

    atomicAdd(&ssum[c0 + 0], ls0); atomicAdd(&ssq[c0 + 0], lq0);
    atomicAdd(&ssum[c0 + 1], ls1); atomicAdd(&ssq[c0 + 1], lq1);
    atomicAdd(&ssum[c0 + 2], ls2); atomicAdd(&ssq[c0 + 2], lq2);
    atomicAdd(&ssum[c0 + 3], ls3); atomicAdd(&ssq[c0 + 3], lq3);
    __syncthreads();
    if (threadIdx.x < Hd) {
        atomicAdd(&g_sum[threadIdx.x], (double)ssum[threadIdx.x]);
        atomicAdd(&g_sumsq[threadIdx.x], (double)ssq[threadIdx.x]);
    }
}

// ---------------- BN fold + apply ----------------
__global__ void bn_stats(int n, const float* __restrict__ gamma, const float* __restrict__ beta) {
    int c = threadIdx.x;
    if (c >= Hd) return;
    double mean = g_sum[c] / n;
    double var  = g_sumsq[c] / n - mean * mean;
    if (var < 0.0) var = 0.0;
    float inv = (float)rsqrt(var + 1e-5);
    float sc = inv * gamma[c];
    g_scale[c] = sc;
    g_shift[c] = beta[c] - (float)mean * sc;
    g_sum[c] = 0.0;
    g_sumsq[c] = 0.0;
}

__global__ void bn_apply_fused(int n, const int* __restrict__ batch, int last) {
    long stride = (long)gridDim.x * blockDim.x;
    long total = (long)n * Hd;
    for (long i = (long)blockIdx.x * blockDim.x + threadIdx.x; i < total; i += stride) {
        int c = (int)(i & 127);
        float v = fmaxf(g_h[i] * g_scale[c] + g_shift[c], 0.f);
        if (!last) {
            g_h[i] = v;
            __nv_bfloat16 hi = __float2bfloat16(v);
            g_Ahi[i] = hi;
            g_Alo[i] = __float2bfloat16(v - __bfloat162float(hi));
        } else {
            int node = (int)(i >> 7);
            atomicAdd(&g_pool[batch[node] * Hd + c], v);
        }
    }
}

__global__ void classify(const float* __restrict__ W, const float* __restrict__ b,
                         float* __restrict__ out) {
    int g = blockIdx.x;
    int c = threadIdx.x;
    if (c >= Cc) return;
    float inv = 1.f / fmaxf(g_cnt[g], 1.f);
    float acc = 0.f;
    #pragma unroll 8
    for (int h = 0; h < Hd; h++) acc += g_pool[g * Hd + h] * W[h * Cc + c];
    out[g * Cc + c] = acc * inv + b[c];
}

// ---------------- host orchestration ----------------
extern "C" void kernel_launch(void* const* d_in, const int* in_sizes, int n_in,
                              void* d_out, int out_size)
{
    const float* x     = (const float*)d_in[0];
    const int*   ei    = (const int*)d_in[1];
    const int*   batch = (const int*)d_in[2];
    const float* Wq1 = (const float*)d_in[3];
    const float* bq1 = (const float*)d_in[4];
    const float* Wk1 = (const float*)d_in[5];
    const float* bk1 = (const float*)d_in[6];
    const float* Wv1 = (const float*)d_in[7];
    const float* bv1 = (const float*)d_in[8];
    const float* Ws1 = (const float*)d_in[9];
    const float* bs1 = (const float*)d_in[10];
    const float* bn1g = (const float*)d_in[11];
    const float* bn1b = (const float*)d_in[12];
    const float* Wq = (const float*)d_in[13];
    const float* bq = (const float*)d_in[14];
    const float* Wk = (const float*)d_in[15];
    const float* bk = (const float*)d_in[16];
    const float* Wv = (const float*)d_in[17];
    const float* bv = (const float*)d_in[18];
    const float* Ws = (const float*)d_in[19];
    const float* bs = (const float*)d_in[20];
    const float* bng = (const float*)d_in[21];
    const float* bnb = (const float*)d_in[22];
    const float* linW = (const float*)d_in[23];
    const float* linb = (const float*)d_in[24];

    int n = in_sizes[0] / IN_DIM;
    int E = in_sizes[1] / 2;
    int ntiles = (n + 127) / 128;
    const int* src = ei;
    const int* dst = ei + E;

    const int GEMM_SMEM = 2 * 4 * TSZ * 2;   // 81920 bytes
    cudaFuncSetAttribute(gemm_mma<IN_DIM>, cudaFuncAttributeMaxDynamicSharedMemorySize, GEMM_SMEM);
    cudaFuncSetAttribute(gemm_mma<Hd>,     cudaFuncAttributeMaxDynamicSharedMemorySize, GEMM_SMEM);

    // launch #1: fused layer-1 prep (A split K=64 + B split + bias)
    prep_layer1<<<1024, 256>>>(x, n, ntiles, Wq1, Wk1, Wv1, Ws1, bq1, bk1, bv1, bs1);
    // launch #2: init (deg zero, BN sums, pool, graph counts, pad A image)
    setup_init<<<(n + 255) / 256, 256>>>(batch, n, ntiles);
    // launch #3: degree count
    csr_count<<<(E + 255) / 256, 256>>>(dst, E);
    // launch #4: GEMM layer 1  (this is the launch ncu samples)
    gemm_mma<IN_DIM><<<dim3(ntiles, 4), 256, GEMM_SMEM>>>(n);
    // launch #5-6: scan + scatter
    scan_block<<<1, 1024>>>(n);
    csr_scatter<<<(E + 255) / 256, 256>>>(src, dst, E);
    // layer-1 attention + BN
    attn_fused<<<2048, 256>>>(n);
    bn_stats<<<1, 128>>>(n, bn1g, bn1b);
    bn_apply_fused<<<512, 256>>>(n, batch, 0);

    // hidden layers
    for (int i = 0; i < Ld; i++) {
        prep_B128<<<(512 * Hd + 255) / 256, 256>>>(
            Wq + (size_t)i * Hd * Hd, Wk + (size_t)i * Hd * Hd,
            Wv + (size_t)i * Hd * Hd, Ws + (size_t)i * Hd * Hd,
            bq + i * Hd, bk + i * Hd, bv + i * Hd, bs + i * Hd);
        gemm_mma<Hd><<<dim3(ntiles, 4), 256, GEMM_SMEM>>>(n);
        attn_fused<<<2048, 256>>>(n);
        bn_stats<<<1, 128>>>(n, bng + i * Hd, bnb + i * Hd);
        bn_apply_fused<<<512, 256>>>(n, batch, (i == Ld - 1) ? 1 : 0);
    }

    classify<<<Gg, 32>>>(linW, linb, (float*)d_out);
}

// round 6
// speedup vs baseline: 2.4261x; 1.0449x over previous
#include <cuda_runtime.h>
#include <cuda_bf16.h>
#include <math.h>
#include <stdint.h>

// Problem constants
#define Nn 100000
#define Ee 600000
#define IN_DIM 64
#define Hd 128
#define Ld 3
#define Gg 256
#define Cc 10
#define NTILES ((Nn + 127) / 128)

// ---------------- device scratch ----------------
__device__ float  g_h[(size_t)Nn * Hd];                        // pre-BN features
__device__ float  g_q[(size_t)Nn * Hd];                        // query (fp32)
__device__ float  g_s[(size_t)Nn * Hd];                        // skip (fp32)
__device__ __align__(16) __nv_bfloat16 g_kv[(size_t)Nn * 256]; // per node: k[0:128] | v[128:256] bf16
__device__ double g_sum[Hd];
__device__ double g_sumsq[Hd];
__device__ float  g_scale[Hd];
__device__ float  g_shift[Hd];
__device__ float  g_pool[Gg * Hd];
__device__ float  g_cnt[Gg];
// CSR
__device__ int    g_deg[Nn];
__device__ int    g_off[Nn + 1];
__device__ int    g_srcSorted[Ee];
// bf16 hi/lo split staging (K-major)
__device__ __align__(16) __nv_bfloat16 g_Ahi[(size_t)NTILES * 128 * 128];
__device__ __align__(16) __nv_bfloat16 g_Alo[(size_t)NTILES * 128 * 128];
__device__ __align__(16) __nv_bfloat16 g_Bhi[512 * 128];
__device__ __align__(16) __nv_bfloat16 g_Blo[512 * 128];
__device__ float  g_bias[512];

// ---------------- asm helpers ----------------
__device__ __forceinline__ uint32_t smem_u32(const void* p) {
    uint32_t a;
    asm("{ .reg .u64 t; cvta.to.shared.u64 t, %1; cvt.u32.u64 %0, t; }" : "=r"(a) : "l"(p));
    return a;
}

__device__ __forceinline__ void mma16816(float* d,
    uint32_t a0, uint32_t a1, uint32_t a2, uint32_t a3,
    uint32_t b0, uint32_t b1)
{
    asm volatile(
        "mma.sync.aligned.m16n8k16.row.col.f32.bf16.bf16.f32 "
        "{%0,%1,%2,%3}, {%4,%5,%6,%7}, {%8,%9}, {%0,%1,%2,%3};"
        : "+f"(d[0]), "+f"(d[1]), "+f"(d[2]), "+f"(d[3])
        : "r"(a0), "r"(a1), "r"(a2), "r"(a3), "r"(b0), "r"(b1));
}

__device__ __forceinline__ void ldsm4(uint32_t* r, uint32_t addr) {
    asm volatile("ldmatrix.sync.aligned.m8n8.x4.shared.b16 {%0,%1,%2,%3}, [%4];"
        : "=r"(r[0]), "=r"(r[1]), "=r"(r[2]), "=r"(r[3]) : "r"(addr));
}

#define CP_ASYNC16(dst, src) \
    asm volatile("cp.async.cg.shared.global [%0], [%1], 16;" :: "r"(dst), "l"(src))
#define CP_COMMIT()  asm volatile("cp.async.commit_group;" ::: "memory")

__device__ __forceinline__ float4 ld_bf4(const __nv_bfloat16* p) {
    uint2 u = *(const uint2*)p;
    __nv_bfloat162 a = *reinterpret_cast<__nv_bfloat162*>(&u.x);
    __nv_bfloat162 b = *reinterpret_cast<__nv_bfloat162*>(&u.y);
    float2 fa = __bfloat1622float2(a), fb = __bfloat1622float2(b);
    return make_float4(fa.x, fa.y, fb.x, fb.y);
}

// ---------------- fused layer-1 prep ----------------
__global__ void prep_layer1(const float* __restrict__ x, int n, int ntiles,
                            const float* __restrict__ Wq, const float* __restrict__ Wk,
                            const float* __restrict__ Wv, const float* __restrict__ Ws,
                            const float* __restrict__ bq, const float* __restrict__ bk,
                            const float* __restrict__ bv, const float* __restrict__ bs)
{
    long aTot = (long)ntiles * 128 * IN_DIM;
    long bTot = 512 * IN_DIM;
    long total = aTot + bTot + 512;
    long stride = (long)gridDim.x * blockDim.x;
    for (long idx = (long)blockIdx.x * blockDim.x + threadIdx.x; idx < total; idx += stride) {
        if (idx < aTot) {
            long row = idx / IN_DIM;
            int  k = (int)(idx % IN_DIM);
            float v = (row < n) ? x[row * IN_DIM + k] : 0.f;
            __nv_bfloat16 hi = __float2bfloat16(v);
            g_Ahi[idx] = hi;
            g_Alo[idx] = __float2bfloat16(v - __bfloat162float(hi));
        } else if (idx < aTot + bTot) {
            int j = (int)(idx - aTot);
            int nglob = j / IN_DIM, k = j % IN_DIM;
            int w = nglob >> 7, nloc = nglob & 127;
            const float* W = (w == 0) ? Wq : (w == 1) ? Wk : (w == 2) ? Wv : Ws;
            float v = W[(size_t)k * Hd + nloc];
            __nv_bfloat16 hi = __float2bfloat16(v);
            g_Bhi[j] = hi;
            g_Blo[j] = __float2bfloat16(v - __bfloat162float(hi));
        } else {
            int nglob = (int)(idx - aTot - bTot);
            int w = nglob >> 7, nloc = nglob & 127;
            const float* B = (w == 0) ? bq : (w == 1) ? bk : (w == 2) ? bv : bs;
            g_bias[nglob] = B[nloc];
        }
    }
}

__global__ void prep_B128(const float* __restrict__ Wq, const float* __restrict__ Wk,
                          const float* __restrict__ Wv, const float* __restrict__ Ws,
                          const float* __restrict__ bq, const float* __restrict__ bk,
                          const float* __restrict__ bv, const float* __restrict__ bs) {
    int idx = blockIdx.x * blockDim.x + threadIdx.x;
    if (idx >= 512 * Hd) return;
    int nglob = idx / Hd, k = idx % Hd;
    int w = nglob >> 7, nloc = nglob & 127;
    const float* W = (w == 0) ? Wq : (w == 1) ? Wk : (w == 2) ? Wv : Ws;
    float v = W[(size_t)k * Hd + nloc];
    __nv_bfloat16 hi = __float2bfloat16(v);
    g_Bhi[idx] = hi;
    g_Blo[idx] = __float2bfloat16(v - __bfloat162float(hi));
    if (k == 0) {
        const float* B = (w == 0) ? bq : (w == 1) ? bk : (w == 2) ? bv : bs;
        g_bias[nglob] = B[nloc];
    }
}

// ---------------- GEMM v3: A-resident, loop over 4 N-chunks, cp.async pipelined B ----------------
#define BSTR 40
#define BTSZ (128 * BSTR)

template<int K>
__global__ void __launch_bounds__(256, 2) gemm_mma(int n) {
    constexpr int ASTR = K + 8;
    constexpr int ATSZ = 128 * ASTR;
    constexpr int NK = K / 32;
    extern __shared__ __nv_bfloat16 sm[];
    const int B_OFF = 2 * ATSZ;

    const int tid = threadIdx.x;
    const int tile = blockIdx.x;
    const int wid = tid >> 5, lane = tid & 31;
    const int wm = (wid & 3) * 32, wn = (wid >> 2) * 64;
    const int gid = lane >> 2, tig = lane & 3;
    const uint32_t smb = smem_u32(sm);

    const __nv_bfloat16* aH = g_Ahi + (size_t)tile * 128 * K;
    const __nv_bfloat16* aL = g_Alo + (size_t)tile * 128 * K;

    // stage A (both images, full K) once
    {
        constexpr int ACH = 2 * 128 * (K / 8);
        #pragma unroll
        for (int t = 0; t < ACH / 256; t++) {
            int i = tid + t * 256;
            int img = i / (128 * (K / 8));
            int rem = i % (128 * (K / 8));
            int r = rem / (K / 8), c = rem % (K / 8);
            const __nv_bfloat16* sp = (img ? aL : aH) + (size_t)r * K + c * 8;
            uint32_t d = smb + (uint32_t)(img * ATSZ + r * ASTR + c * 8) * 2;
            CP_ASYNC16(d, sp);
        }
    }

    auto stageB = [&](int buf, int cc, int kt) {
        #pragma unroll
        for (int t = 0; t < 4; t++) {
            int idx = tid + t * 256;
            int img = idx >> 9, rem = idx & 511;
            int r = rem >> 2, c = rem & 3;
            const __nv_bfloat16* sp = (img ? g_Blo : g_Bhi) + (size_t)(cc * 128 + r) * K + kt + c * 8;
            uint32_t d = smb + (uint32_t)(B_OFF + buf * 2 * BTSZ + img * BTSZ + r * BSTR + c * 8) * 2;
            CP_ASYNC16(d, sp);
        }
    };

    stageB(0, 0, 0);
    CP_COMMIT();

    float acc[2][8][4] = {};

    #pragma unroll 1
    for (int p = 0; p < 4 * NK; p++) {
        if (p + 1 < 4 * NK) {
            stageB((p + 1) & 1, (p + 1) / NK, ((p + 1) % NK) * 32);
            CP_COMMIT();
            asm volatile("cp.async.wait_group 1;" ::: "memory");
        } else {
            asm volatile("cp.async.wait_group 0;" ::: "memory");
        }
        __syncthreads();

        const int ktA = (p % NK) * 32;
        const uint32_t bbase = smb + (uint32_t)(B_OFF + (p & 1) * 2 * BTSZ) * 2;

        #pragma unroll
        for (int ks = 0; ks < 2; ks++) {
            const int kb = ks * 16;
            uint32_t ah[2][4], al[2][4];
            #pragma unroll
            for (int mt = 0; mt < 2; mt++) {
                int row = wm + mt * 16 + (lane & 15);
                int col = ktA + kb + ((lane & 16) ? 8 : 0);
                uint32_t ad = smb + (uint32_t)(row * ASTR + col) * 2;
                ldsm4(ah[mt], ad);
                ldsm4(al[mt], ad + ATSZ * 2);
            }
            #pragma unroll
            for (int ntp = 0; ntp < 4; ntp++) {
                int row = wn + ntp * 16 + (lane & 7) + ((lane & 16) ? 8 : 0);
                int col = kb + ((lane & 8) ? 8 : 0);
                uint32_t bd = bbase + (uint32_t)(row * BSTR + col) * 2;
                uint32_t bh[4], bl[4];
                ldsm4(bh, bd);
                ldsm4(bl, bd + BTSZ * 2);
                #pragma unroll
                for (int sub = 0; sub < 2; sub++) {
                    int nt = ntp * 2 + sub;
                    #pragma unroll
                    for (int mt = 0; mt < 2; mt++) {
                        mma16816(acc[mt][nt], ah[mt][0], ah[mt][1], ah[mt][2], ah[mt][3], bh[sub*2], bh[sub*2+1]);
                        mma16816(acc[mt][nt], ah[mt][0], ah[mt][1], ah[mt][2], ah[mt][3], bl[sub*2], bl[sub*2+1]);
                        mma16816(acc[mt][nt], al[mt][0], al[mt][1], al[mt][2], al[mt][3], bh[sub*2], bh[sub*2+1]);
                    }
                }
            }
        }
        __syncthreads();

        if ((p % NK) == NK - 1) {
            const int cc = p / NK;
            #pragma unroll
            for (int mt = 0; mt < 2; mt++) {
                long r0 = (long)tile * 128 + wm + mt * 16 + gid;
                #pragma unroll
                for (int nt = 0; nt < 8; nt++) {
                    int col = wn + nt * 8 + tig * 2;
                    float b0 = g_bias[cc * 128 + col], b1 = g_bias[cc * 128 + col + 1];
                    float v0 = acc[mt][nt][0] + b0, v1 = acc[mt][nt][1] + b1;
                    float v2 = acc[mt][nt][2] + b0, v3 = acc[mt][nt][3] + b1;
                    if (cc == 0) {
                        if (r0 < n)     *(float2*)(g_q + r0 * 128 + col)       = make_float2(v0, v1);
                        if (r0 + 8 < n) *(float2*)(g_q + (r0 + 8) * 128 + col) = make_float2(v2, v3);
                    } else if (cc == 3) {
                        if (r0 < n)     *(float2*)(g_s + r0 * 128 + col)       = make_float2(v0, v1);
                        if (r0 + 8 < n) *(float2*)(g_s + (r0 + 8) * 128 + col) = make_float2(v2, v3);
                    } else {
                        int off = (cc == 2) ? 128 : 0;
                        __nv_bfloat162 p0 = __floats2bfloat162_rn(v0, v1);
                        __nv_bfloat162 p1 = __floats2bfloat162_rn(v2, v3);
                        if (r0 < n)     *(__nv_bfloat162*)(g_kv + r0 * 256 + off + col)       = p0;
                        if (r0 + 8 < n) *(__nv_bfloat162*)(g_kv + (r0 + 8) * 256 + off + col) = p1;
                    }
                    acc[mt][nt][0] = 0.f; acc[mt][nt][1] = 0.f;
                    acc[mt][nt][2] = 0.f; acc[mt][nt][3] = 0.f;
                }
            }
        }
    }
}

// ---------------- setup ----------------
__global__ void setup_init(const int* __restrict__ batch, int n, int ntiles) {
    int idx = blockIdx.x * blockDim.x + threadIdx.x;
    if (idx < n) g_deg[idx] = 0;
    if (idx == 0) g_off[0] = 0;
    if (idx < Hd) { g_sum[idx] = 0.0; g_sumsq[idx] = 0.0; }
    if (idx < Gg * Hd) g_pool[idx] = 0.f;
    if (idx < Gg) {
        int g = idx;
        int lo = 0, hi = n;
        while (lo < hi) { int mid = (lo + hi) >> 1; if (batch[mid] < g) lo = mid + 1; else hi = mid; }
        int lb = lo;
        lo = 0; hi = n;
        while (lo < hi) { int mid = (lo + hi) >> 1; if (batch[mid] <= g) lo = mid + 1; else hi = mid; }
        g_cnt[g] = (float)(lo - lb);
    }
    long pad0 = (long)n * Hd;
    long padN = (long)ntiles * 128 * Hd - pad0;
    if (idx < padN) {
        g_Ahi[pad0 + idx] = __float2bfloat16(0.f);
        g_Alo[pad0 + idx] = __float2bfloat16(0.f);
    }
}

__global__ void csr_count(const int* __restrict__ dst, int E) {
    int e = blockIdx.x * blockDim.x + threadIdx.x;
    if (e < E) atomicAdd(&g_deg[dst[e]], 1);
}

__global__ void __launch_bounds__(1024) scan_block(int n) {
    __shared__ int sh[1024];
    int t = threadIdx.x;
    int chunk = (n + 1023) >> 10;
    int s0 = min(t * chunk, n), s1 = min(s0 + chunk, n);
    int s = 0;
    for (int i = s0; i < s1; i++) s += g_deg[i];
    sh[t] = s;
    __syncthreads();
    #pragma unroll
    for (int d = 1; d < 1024; d <<= 1) {
        int v = (t >= d) ? sh[t - d] : 0;
        __syncthreads();
        sh[t] += v;
        __syncthreads();
    }
    int run = (t == 0) ? 0 : sh[t - 1];
    for (int i = s0; i < s1; i++) {
        int d = g_deg[i];
        g_deg[i] = run;
        run += d;
        g_off[i + 1] = run;
    }
}

__global__ void csr_scatter(const int* __restrict__ src, const int* __restrict__ dst, int E) {
    int e = blockIdx.x * blockDim.x + threadIdx.x;
    if (e >= E) return;
    int pos = atomicAdd(&g_deg[dst[e]], 1);
    g_srcSorted[pos] = src[e];
}

// ---------------- fused attention (bf16 k/v gathers) ----------------
__global__ void __launch_bounds__(256) attn_fused(int n) {
    __shared__ float ssum[Hd], ssq[Hd];
    for (int i = threadIdx.x; i < Hd; i += 256) { ssum[i] = 0.f; ssq[i] = 0.f; }
    __syncthreads();

    const int lane = threadIdx.x & 31;
    const int c0 = lane * 4;
    const int wstride = gridDim.x * 8;
    float ls0 = 0.f, ls1 = 0.f, ls2 = 0.f, ls3 = 0.f;
    float lq0 = 0.f, lq1 = 0.f, lq2 = 0.f, lq3 = 0.f;

    for (int node = blockIdx.x * 8 + (threadIdx.x >> 5); node < n; node += wstride) {
        const int off0 = g_off[node];
        const int deg  = g_off[node + 1] - off0;
        const float4 q = *(const float4*)(g_q + (size_t)node * 128 + c0);

        float m = -INFINITY, sum = 0.f;
        float ax = 0.f, ay = 0.f, az = 0.f, aw = 0.f;

        uint2 kc = make_uint2(0, 0), vc = kc, kn = kc, vn = kc;
        if (deg > 0) {
            const __nv_bfloat16* r0 = g_kv + (size_t)g_srcSorted[off0] * 256;
            kc = *(const uint2*)(r0 + c0);
            vc = *(const uint2*)(r0 + 128 + c0);
        }
        if (deg > 1) {
            const __nv_bfloat16* r1 = g_kv + (size_t)g_srcSorted[off0 + 1] * 256;
            kn = *(const uint2*)(r1 + c0);
            vn = *(const uint2*)(r1 + 128 + c0);
        }
        #pragma unroll 2
        for (int j = 0; j < deg; j++) {
            uint2 ku = kc, vu = vc;
            kc = kn; vc = vn;
            if (j + 2 < deg) {
                const __nv_bfloat16* r2 = g_kv + (size_t)g_srcSorted[off0 + j + 2] * 256;
                kn = *(const uint2*)(r2 + c0);
                vn = *(const uint2*)(r2 + 128 + c0);
            }
            float4 kk = ld_bf4((const __nv_bfloat16*)&ku);
            float p = q.x * kk.x + q.y * kk.y + q.z * kk.z + q.w * kk.w;
            #pragma unroll
            for (int o = 16; o; o >>= 1) p += __shfl_xor_sync(0xffffffffu, p, o);
            p *= 0.08838834764831845f;
            float mn = fmaxf(m, p);
            float r = expf(m - mn);
            float w = expf(p - mn);
            float4 vv = ld_bf4((const __nv_bfloat16*)&vu);
            ax = ax * r + w * vv.x;
            ay = ay * r + w * vv.y;
            az = az * r + w * vv.z;
            aw = aw * r + w * vv.w;
            sum = sum * r + w;
            m = mn;
        }
        float inv = (deg > 0) ? 1.f / sum : 0.f;
        float4 sk = *(const float4*)(g_s + (size_t)node * 128 + c0);
        float h0 = ax * inv + sk.x;
        float h1 = ay * inv + sk.y;
        float h2 = az * inv + sk.z;
        float h3 = aw * inv + sk.w;
        *(float4*)(g_h + (size_t)node * Hd + c0) = make_float4(h0, h1, h2, h3);
        ls0 += h0; ls1 += h1; ls2 += h2; ls3 += h3;
        lq0 += h0 * h0; lq1 += h1 * h1; lq2 += h2 * h2; lq3 += h3 * h3;
    }

    atomicAdd(&ssum[c0 + 0], ls0); atomicAdd(&ssq[c0 + 0], lq0);
    atomicAdd(&ssum[c0 + 1], ls1); atomicAdd(&ssq[c0 + 1], lq1);
    atomicAdd(&ssum[c0 + 2], ls2); atomicAdd(&ssq[c0 + 2], lq2);
    atomicAdd(&ssum[c0 + 3], ls3); atomicAdd(&ssq[c0 + 3], lq3);
    __syncthreads();
    if (threadIdx.x < Hd) {
        atomicAdd(&g_sum[threadIdx.x], (double)ssum[threadIdx.x]);
        atomicAdd(&g_sumsq[threadIdx.x], (double)ssq[threadIdx.x]);
    }
}

// ---------------- BN fold + apply ----------------
__global__ void bn_stats(int n, const float* __restrict__ gamma, const float* __restrict__ beta) {
    int c = threadIdx.x;
    if (c >= Hd) return;
    double mean = g_sum[c] / n;
    double var  = g_sumsq[c] / n - mean * mean;
    if (var < 0.0) var = 0.0;
    float inv = (float)rsqrt(var + 1e-5);
    float sc = inv * gamma[c];
    g_scale[c] = sc;
    g_shift[c] = beta[c] - (float)mean * sc;
    g_sum[c] = 0.0;
    g_sumsq[c] = 0.0;
}

__global__ void bn_apply_fused(int n, const int* __restrict__ batch, int last) {
    long stride = (long)gridDim.x * blockDim.x;
    long total = (long)n * Hd;
    for (long i = (long)blockIdx.x * blockDim.x + threadIdx.x; i < total; i += stride) {
        int c = (int)(i & 127);
        float v = fmaxf(g_h[i] * g_scale[c] + g_shift[c], 0.f);
        if (!last) {
            __nv_bfloat16 hi = __float2bfloat16(v);
            g_Ahi[i] = hi;
            g_Alo[i] = __float2bfloat16(v - __bfloat162float(hi));
        } else {
            int node = (int)(i >> 7);
            atomicAdd(&g_pool[batch[node] * Hd + c], v);
        }
    }
}

__global__ void classify(const float* __restrict__ W, const float* __restrict__ b,
                         float* __restrict__ out) {
    int g = blockIdx.x;
    int c = threadIdx.x;
    if (c >= Cc) return;
    float inv = 1.f / fmaxf(g_cnt[g], 1.f);
    float acc = 0.f;
    #pragma unroll 8
    for (int h = 0; h < Hd; h++) acc += g_pool[g * Hd + h] * W[h * Cc + c];
    out[g * Cc + c] = acc * inv + b[c];
}

// ---------------- host orchestration ----------------
extern "C" void kernel_launch(void* const* d_in, const int* in_sizes, int n_in,
                              void* d_out, int out_size)
{
    const float* x     = (const float*)d_in[0];
    const int*   ei    = (const int*)d_in[1];
    const int*   batch = (const int*)d_in[2];
    const float* Wq1 = (const float*)d_in[3];
    const float* bq1 = (const float*)d_in[4];
    const float* Wk1 = (const float*)d_in[5];
    const float* bk1 = (const float*)d_in[6];
    const float* Wv1 = (const float*)d_in[7];
    const float* bv1 = (const float*)d_in[8];
    const float* Ws1 = (const float*)d_in[9];
    const float* bs1 = (const float*)d_in[10];
    const float* bn1g = (const float*)d_in[11];
    const float* bn1b = (const float*)d_in[12];
    const float* Wq = (const float*)d_in[13];
    const float* bq = (const float*)d_in[14];
    const float* Wk = (const float*)d_in[15];
    const float* bk = (const float*)d_in[16];
    const float* Wv = (const float*)d_in[17];
    const float* bv = (const float*)d_in[18];
    const float* Ws = (const float*)d_in[19];
    const float* bs = (const float*)d_in[20];
    const float* bng = (const float*)d_in[21];
    const float* bnb = (const float*)d_in[22];
    const float* linW = (const float*)d_in[23];
    const float* linb = (const float*)d_in[24];

    int n = in_sizes[0] / IN_DIM;
    int E = in_sizes[1] / 2;
    int ntiles = (n + 127) / 128;
    const int* src = ei;
    const int* dst = ei + E;

    const int SMEM64  = (2 * 128 * (IN_DIM + 8) + 4 * BTSZ) * 2;  // 77824
    const int SMEM128 = (2 * 128 * (Hd + 8) + 4 * BTSZ) * 2;      // 110592
    cudaFuncSetAttribute(gemm_mma<IN_DIM>, cudaFuncAttributeMaxDynamicSharedMemorySize, SMEM64);
    cudaFuncSetAttribute(gemm_mma<Hd>,     cudaFuncAttributeMaxDynamicSharedMemorySize, SMEM128);

    // #1 fused layer-1 prep, #2 init, #3 degree count
    prep_layer1<<<1024, 256>>>(x, n, ntiles, Wq1, Wk1, Wv1, Ws1, bq1, bk1, bv1, bs1);
    setup_init<<<(n + 255) / 256, 256>>>(batch, n, ntiles);
    csr_count<<<(E + 255) / 256, 256>>>(dst, E);
    // #4 GEMM layer 1 (profiled launch)
    gemm_mma<IN_DIM><<<ntiles, 256, SMEM64>>>(n);
    // CSR finish
    scan_block<<<1, 1024>>>(n);
    csr_scatter<<<(E + 255) / 256, 256>>>(src, dst, E);
    // layer-1 attention + BN
    attn_fused<<<2048, 256>>>(n);
    bn_stats<<<1, 128>>>(n, bn1g, bn1b);
    bn_apply_fused<<<512, 256>>>(n, batch, 0);

    for (int i = 0; i < Ld; i++) {
        prep_B128<<<(512 * Hd + 255) / 256, 256>>>(
            Wq + (size_t)i * Hd * Hd, Wk + (size_t)i * Hd * Hd,
            Wv + (size_t)i * Hd * Hd, Ws + (size_t)i * Hd * Hd,
            bq + i * Hd, bk + i * Hd, bv + i * Hd, bs + i * Hd);
        gemm_mma<Hd><<<ntiles, 256, SMEM128>>>(n);
        attn_fused<<<2048, 256>>>(n);
        bn_stats<<<1, 128>>>(n, bng + i * Hd, bnb + i * Hd);
        bn_apply_fused<<<512, 256>>>(n, batch, (i == Ld - 1) ? 1 : 0);
    }

    classify<<<Gg, 32>>>(linW, linb, (float*)d_out);
}